// round 9
// baseline (speedup 1.0000x reference)
#include <cuda_runtime.h>
#include <math.h>

typedef unsigned long long u64;

// ---------------- problem constants ----------------
static const int NSUP  = 115;
static const int NQRY  = 23;
static const int NTOT  = 138;
static const int NCLS  = 23;

// ---------------- device scratch ----------------
__device__ float g_buf0[(size_t)NTOT*64*128*128];
__device__ float g_buf1[(size_t)NTOT*64*64*64];
__device__ float g_cat [(size_t)NTOT*2048];
__device__ float g_tmp [(size_t)NTOT*1024];
__device__ float g_h2  [(size_t)NTOT*1024];
__device__ float g_feat[(size_t)NTOT*1024];
__device__ float g_agg [(size_t)NTOT*1024];
__device__ float g_cnt [NTOT];
__device__ float g_b   [NQRY*NSUP];
__device__ float g_dis [NQRY*NCLS];

// ---------------- packed f32x2 helpers ----------------
__device__ __forceinline__ u64 pk2(float x, float y){
    u64 r; asm("mov.b64 %0, {%1, %2};" : "=l"(r) : "f"(x), "f"(y)); return r;
}
__device__ __forceinline__ void fma2(u64 &d, u64 a, u64 b){
    asm("fma.rn.f32x2 %0, %1, %2, %0;" : "+l"(d) : "l"(a), "l"(b));
}
__device__ __forceinline__ float2 up2(u64 a){
    float2 r; asm("mov.b64 {%0, %1}, %2;" : "=f"(r.x), "=f"(r.y) : "l"(a)); return r;
}
__device__ __forceinline__ u64 cmp2(u64 a, u64 b){ return (a >> 32) | (b << 32); }

// ---------------- conv1n: 3->64, weights-in-registers, 2 CTAs/SM (R7 proven) ----------------
__global__ void __launch_bounds__(512, 2)
conv1n_kernel(const float* __restrict__ sx,
              const float* __restrict__ qx,
              const float* __restrict__ w,
              const float* __restrict__ bias,
              float* __restrict__ out)
{
    __shared__ __align__(16) float sTile[3][10][18];
    __shared__ u64 sW[64][27];

    const int tid = threadIdx.x;
    const int img = blockIdx.y;
    const int tx = blockIdx.x & 15;
    const int ty = blockIdx.x >> 4;
    const int gx0 = tx*16, gy0 = ty*8;
    const float* inImg = (img < NSUP) ? sx + (size_t)img*3*65536
                                      : qx + (size_t)(img-NSUP)*3*65536;

    for (int idx = tid; idx < 540; idx += 512){
        int k = idx/180; int rem = idx - k*180;
        int r = rem/18, c = rem - r*18;
        int iy = gy0 - 1 + r, ix = gx0 - 1 + c;
        float v = 0.f;
        if ((unsigned)iy < 256u && (unsigned)ix < 256u)
            v = inImg[k*65536 + iy*256 + ix];
        sTile[k][r][c] = v;
    }
    for (int idx = tid; idx < 1728; idx += 512){
        float v = w[idx];
        sW[idx/27][idx%27] = pk2(v, v);
    }
    __syncthreads();

    const int oc  = tid >> 3;
    const int sid = tid & 7;
    const u64* tbase = (const u64*)sTile;

    u64 acc[8];
    #pragma unroll
    for (int r = 0; r < 8; r++) acc[r] = 0ull;

    #pragma unroll
    for (int ci = 0; ci < 3; ci++){
        u64 wr[9];
        #pragma unroll
        for (int t = 0; t < 9; t++) wr[t] = sW[oc][ci*9 + t];
        #pragma unroll
        for (int tr = 0; tr < 10; tr++){
            u64 T0 = tbase[(ci*10 + tr)*9 + sid];
            u64 T2 = tbase[(ci*10 + tr)*9 + sid + 1];
            u64 T1 = cmp2(T0, T2);
            #pragma unroll
            for (int dy = 0; dy < 3; dy++){
                const int r = tr - dy;
                if (r >= 0 && r < 8){
                    fma2(acc[r], T0, wr[dy*3+0]);
                    fma2(acc[r], T1, wr[dy*3+1]);
                    fma2(acc[r], T2, wr[dy*3+2]);
                }
            }
        }
    }

    float b = bias[oc];
    const int pxl = tx*8 + sid;
    const int py0 = ty*4;
    float* op = out + ((size_t)img*64 + oc)*16384;
    #pragma unroll
    for (int i = 0; i < 4; i++){
        float2 a0 = up2(acc[2*i]), a1 = up2(acc[2*i+1]);
        float m = fmaxf(fmaxf(a0.x, a0.y), fmaxf(a1.x, a1.y)) + b;
        op[(py0 + i)*128 + pxl] = fmaxf(m, 0.f);
    }
}

// ---------------- conv64f: warp = 16 ocg x 2 pos (broadcast P loads), padded weights ----------------
// 512 thr: ocg = tid&15 (4 oc each), pos = tid>>4 (pr=pos&3, px=pos>>2)
// weight buffer padded: 289 u64 per ocg-block -> bank-conflict-free across 16 ocg
template<int IN_H>
__global__ void __launch_bounds__(512,1)
conv64f_kernel(const float* __restrict__ in,
               const float* __restrict__ w,
               const float* __restrict__ bias,
               float* __restrict__ out,
               int outImgStride)
{
    constexpr int PH    = IN_H/2;
    constexpr int TILES = PH/8;
    constexpr int TI    = 18;
    constexpr int CHUNK = 8;
    constexpr int HH    = IN_H*IN_H;
    constexpr int PKN   = CHUNK*TI*17;   // 2448
    constexpr int WN    = 64*CHUNK*9;    // 4608 (unpadded count)
    constexpr int WNP   = WN + 16;       // 4624 padded (1 u64 pad per ocg block of 288)

    extern __shared__ __align__(16) unsigned char sm[];
    u64* sW  = (u64*)sm;                          // [3][WNP]
    u64* sPk = (u64*)(sm + 3*(size_t)WNP*8);      // [3][PKN]

    const int tid = threadIdx.x;
    const int ocg = tid & 15;          // NEW: warp spans 16 ocg
    const int pos = tid >> 4;          // NEW: 2 pos per warp
    const int pr  = pos & 3;
    const int px  = pos >> 2;
    const int img = blockIdx.y;
    const int tpy = blockIdx.x / TILES, tpx = blockIdx.x % TILES;
    const int cy0 = tpy*16, cx0 = tpx*16;
    const float* inImg = in + (size_t)img*64*HH;

    int  eoff[5];
    bool ep0[5], ep1[5];
    #pragma unroll
    for (int j=0;j<5;j++){
        int e = tid + j*512;
        bool v = e < PKN;
        int ee = v ? e : 0;
        int k = ee/306, rem = ee - k*306;
        int r = rem/17,  s  = rem - r*17;
        int c0 = (s<9) ? 2*s : 2*(s-9)+1;
        int iy = cy0-1+r, ix0 = cx0-1+c0;
        bool rowok = (unsigned)iy < (unsigned)IN_H;
        ep0[j] = v && rowok && (unsigned)ix0     < (unsigned)IN_H;
        ep1[j] = v && rowok && (unsigned)(ix0+1) < (unsigned)IN_H;
        eoff[j] = k*HH + iy*IN_H + ix0;
    }
    int gwoff[9], wdst[9];
    #pragma unroll
    for (int j=0;j<9;j++){
        int we = tid + j*512;             // linear weight index 0..4607
        int oc = we/72, rem = we - oc*72;
        int k = rem/9,  t  = rem - k*9;
        gwoff[j] = (oc*64 + k)*9 + t;
        wdst[j]  = we + we/288;           // padded destination
    }

    u64 acc[4][4];
    #pragma unroll
    for (int o=0;o<4;o++)
        #pragma unroll
        for (int cc=0;cc<4;cc++) acc[o][cc] = 0ull;

    float f[5][2], wr[9];
    const float* pIn = inImg;
    const float* pW  = w;

    // ---- prologue: stage chunk0 -> store buf0; stage chunk1 ----
    #pragma unroll
    for (int j=0;j<5;j++){
        f[j][0] = ep0[j] ? pIn[eoff[j]]   : 0.f;
        f[j][1] = ep1[j] ? pIn[eoff[j]+1] : 0.f;
    }
    #pragma unroll
    for (int j=0;j<9;j++) wr[j] = pW[gwoff[j]];
    pIn += CHUNK*HH; pW += 72;

    #pragma unroll
    for (int j=0;j<5;j++){
        int e = tid + j*512;
        if (e < PKN) *(float2*)(sPk + e) = make_float2(f[j][0], f[j][1]);
    }
    #pragma unroll
    for (int j=0;j<9;j++)
        *(float2*)(sW + wdst[j]) = make_float2(wr[j], wr[j]);

    #pragma unroll
    for (int j=0;j<5;j++){
        f[j][0] = ep0[j] ? pIn[eoff[j]]   : 0.f;
        f[j][1] = ep1[j] ? pIn[eoff[j]+1] : 0.f;
    }
    #pragma unroll
    for (int j=0;j<9;j++) wr[j] = pW[gwoff[j]];
    pIn += CHUNK*HH; pW += 72;

    __syncthreads();

    int rb = 0, wb = 1;
    #pragma unroll 1
    for (int c = 0; c < 8; c++){
        // store staged chunk c+1 into wb -- overlaps with FMA below
        if (c < 7){
            u64* pkw = sPk + wb*PKN;
            u64* ww  = sW  + wb*WNP;
            #pragma unroll
            for (int j=0;j<5;j++){
                int e = tid + j*512;
                if (e < PKN) *(float2*)(pkw + e) = make_float2(f[j][0], f[j][1]);
            }
            #pragma unroll
            for (int j=0;j<9;j++)
                *(float2*)(ww + wdst[j]) = make_float2(wr[j], wr[j]);
        }
        // stage chunk c+2
        if (c < 6){
            #pragma unroll
            for (int j=0;j<5;j++){
                f[j][0] = ep0[j] ? pIn[eoff[j]]   : 0.f;
                f[j][1] = ep1[j] ? pIn[eoff[j]+1] : 0.f;
            }
            #pragma unroll
            for (int j=0;j<9;j++) wr[j] = pW[gwoff[j]];
            pIn += CHUNK*HH; pW += 72;
        }

        // FMA on rb
        const u64* pkb = sPk + rb*PKN;
        const u64* wbb = sW  + rb*WNP + ocg*289;   // padded per-ocg base
        #pragma unroll
        for (int k=0;k<CHUNK;k++){
            const u64* prow = pkb + (k*TI + 4*pr)*17;
            u64 P[6][3];
            #pragma unroll
            for (int r=0;r<6;r++){
                P[r][0] = prow[r*17 + px];
                P[r][1] = prow[r*17 + 9 + px];
                P[r][2] = prow[r*17 + px + 1];
            }
            #pragma unroll
            for (int o=0;o<4;o++){
                const u64* wp = wbb + (o*8 + k)*9;
                #pragma unroll
                for (int dy=0;dy<3;dy++){
                    u64 w0 = wp[dy*3+0], w1 = wp[dy*3+1], w2 = wp[dy*3+2];
                    #pragma unroll
                    for (int cc=0;cc<4;cc++) fma2(acc[o][cc], P[cc+dy][0], w0);
                    #pragma unroll
                    for (int cc=0;cc<4;cc++) fma2(acc[o][cc], P[cc+dy][1], w1);
                    #pragma unroll
                    for (int cc=0;cc<4;cc++) fma2(acc[o][cc], P[cc+dy][2], w2);
                }
            }
        }

        if (c == 7) break;
        __syncthreads();
        rb = wb; wb = (wb == 2) ? 0 : wb + 1;
    }

    const int gx  = tpx*8 + px;
    const int gy0 = tpy*8 + 2*pr;
    #pragma unroll
    for (int o=0;o<4;o++){
        int oc = ocg*4 + o;
        float b = bias[oc];
        float2 a0 = up2(acc[o][0]), a1 = up2(acc[o][1]);
        float2 a2 = up2(acc[o][2]), a3 = up2(acc[o][3]);
        float m0 = fmaxf(fmaxf(a0.x,a0.y), fmaxf(a1.x,a1.y)) + b; m0 = fmaxf(m0, 0.f);
        float m1 = fmaxf(fmaxf(a2.x,a2.y), fmaxf(a3.x,a3.y)) + b; m1 = fmaxf(m1, 0.f);
        float* op = out + (size_t)img*outImgStride + (size_t)oc*PH*PH;
        op[(size_t)gy0*PH + gx]     = m0;
        op[(size_t)(gy0+1)*PH + gx] = m1;
    }
}

// ---------------- conv6 (proven conv64_kernel<8,4>) ----------------
template<int IN_H, int TILE_P>
__global__ void conv64_kernel(const float* __restrict__ in,
                              const float* __restrict__ w,
                              const float* __restrict__ bias,
                              float* __restrict__ out,
                              int outImgStride)
{
    constexpr int PH    = IN_H/2;
    constexpr int TILES = PH / TILE_P;
    constexpr int TI    = TILE_P*2 + 2;
    constexpr int POS   = TILE_P*TILE_P;
    constexpr int NT    = POS*8;
    constexpr int CHUNK = 8;

    __shared__ __align__(16) float sIn[CHUNK][TI][TI];
    __shared__ u64 sW[64][CHUNK][9];

    const int tid = threadIdx.x;
    const int pos = tid & (POS-1);
    const int ocg = tid / POS;
    const int py = pos / TILE_P, px = pos % TILE_P;
    const int img = blockIdx.y;
    const int tpy = blockIdx.x / TILES, tpx = blockIdx.x % TILES;
    const int cy0 = tpy*TILE_P*2, cx0 = tpx*TILE_P*2;
    const float* inImg = in + (size_t)img*64*IN_H*IN_H;

    u64 accA[8], accB[8];
    #pragma unroll
    for (int i=0;i<8;i++){ accA[i]=0ull; accB[i]=0ull; }

    for (int ci0 = 0; ci0 < 64; ci0 += CHUNK){
        for (int idx = tid; idx < CHUNK*TI*TI; idx += NT){
            int k = idx/(TI*TI), rem = idx%(TI*TI);
            int r = rem/TI, c = rem%TI;
            int iy = cy0-1+r, ix = cx0-1+c;
            float v = 0.f;
            if (iy>=0 && iy<IN_H && ix>=0 && ix<IN_H)
                v = inImg[(size_t)(ci0+k)*IN_H*IN_H + (size_t)iy*IN_H + ix];
            sIn[k][r][c] = v;
        }
        for (int idx = tid; idx < 64*CHUNK*9; idx += NT){
            int oc = idx/(CHUNK*9), rem = idx%(CHUNK*9);
            int k = rem/9, t = rem%9;
            float wv = w[(oc*64 + (ci0+k))*9 + t];
            sW[oc][k][t] = pk2(wv, wv);
        }
        __syncthreads();

        #pragma unroll
        for (int k=0;k<CHUNK;k++){
            u64 P[4][3];
            #pragma unroll
            for (int r=0;r<4;r++){
                float2 a = *(const float2*)&sIn[k][2*py+r][2*px];
                float2 b = *(const float2*)&sIn[k][2*py+r][2*px+2];
                P[r][0] = pk2(a.x, a.y);
                P[r][1] = pk2(a.y, b.x);
                P[r][2] = pk2(b.x, b.y);
            }
            #pragma unroll
            for (int o=0;o<8;o++){
                const u64* wp = &sW[ocg*8+o][k][0];
                #pragma unroll
                for (int dy=0;dy<3;dy++){
                    #pragma unroll
                    for (int dx=0;dx<3;dx++){
                        u64 wv = wp[dy*3+dx];
                        fma2(accA[o], P[dy][dx],   wv);
                        fma2(accB[o], P[dy+1][dx], wv);
                    }
                }
            }
        }
        __syncthreads();
    }

    const int gy = tpy*TILE_P+py, gx = tpx*TILE_P+px;
    #pragma unroll
    for (int o=0;o<8;o++){
        int oc = ocg*8+o;
        float2 ca = up2(accA[o]); float2 cb = up2(accB[o]);
        float m = fmaxf(fmaxf(ca.x,ca.y), fmaxf(cb.x,cb.y)) + bias[oc];
        m = fmaxf(m, 0.f);
        out[(size_t)img*outImgStride + (size_t)oc*PH*PH + (size_t)gy*PH + gx] = m;
    }
}

// ---------------- small kernels (proven) ----------------
__global__ void zero_kernel(float* __restrict__ p, int n){
    int i = blockIdx.x*256 + threadIdx.x;
    if (i < n) p[i] = 0.f;
}

__global__ void scatter_kernel(const float* __restrict__ feat, int stride, int colOff,
                               const int* __restrict__ ei, int E, int base,
                               float* __restrict__ agg, float* __restrict__ cnt)
{
    int e = blockIdx.x;
    int src = ei[e], dst = ei[E + e];
    const float* f = feat + (size_t)(base+src)*stride + colOff;
    float* a = agg + (size_t)(base+dst)*1024;
    for (int d = threadIdx.x; d < 1024; d += blockDim.x)
        atomicAdd(&a[d], f[d]);
    if (threadIdx.x == 0) atomicAdd(&cnt[base+dst], 1.f);
}

__global__ void combine_kernel(const float* __restrict__ feat, int fstride, int fcolOff,
                               const float* __restrict__ agg, const float* __restrict__ cnt,
                               float* __restrict__ outp, int ostride, int ocolOff)
{
    int i = blockIdx.x*256 + threadIdx.x;
    if (i >= NTOT*1024) return;
    int n = i >> 10, d = i & 1023;
    float c = fmaxf(cnt[n], 1.f);
    float fv = feat[(size_t)n*fstride + fcolOff + d];
    outp[(size_t)n*ostride + ocolOff + d] = (agg[i]/c) * fv;
}

__global__ void gemm_bias_kernel(const float* __restrict__ A, int lda,
                                 const float* __restrict__ W,
                                 const float* __restrict__ bias,
                                 float* __restrict__ C, int M, int K)
{
    __shared__ float sA[16][17];
    __shared__ float sB[16][64];
    int tx = threadIdx.x & 15, ty = threadIdx.x >> 4;
    int n0 = blockIdx.x*64, m0 = blockIdx.y*16;
    float acc[4] = {0.f,0.f,0.f,0.f};
    for (int k0 = 0; k0 < K; k0 += 16){
        int m = m0 + ty;
        sA[ty][tx] = (m < M) ? A[(size_t)m*lda + k0 + tx] : 0.f;
        #pragma unroll
        for (int j=0;j<4;j++)
            sB[ty][tx*4+j] = W[(size_t)(k0+ty)*1024 + n0 + tx*4 + j];
        __syncthreads();
        #pragma unroll
        for (int kk=0;kk<16;kk++){
            float a = sA[ty][kk];
            #pragma unroll
            for (int j=0;j<4;j++) acc[j] += a * sB[kk][tx*4+j];
        }
        __syncthreads();
    }
    int m = m0 + ty;
    if (m < M){
        #pragma unroll
        for (int j=0;j<4;j++)
            C[(size_t)m*1024 + n0 + tx*4 + j] = acc[j] + bias[n0 + tx*4 + j];
    }
}

__global__ void pair_kernel(const float* __restrict__ feat,
                            const float* __restrict__ center,
                            float* __restrict__ bmat)
{
    int s = blockIdx.x, q = blockIdx.y;
    const float* qf = feat + (size_t)(NSUP+q)*1024;
    const float* sf = feat + (size_t)s*1024;
    const float* cf = center + (size_t)(s/5)*1024;
    __shared__ float su[1024];
    __shared__ float rA[256], rB[256], rC[256];
    __shared__ float sS1, sS2;
    int tid = threadIdx.x;

    float S1 = 0.f, S2 = 0.f, M = -1e30f;
    for (int d = tid; d < 1024; d += 256){
        float qd = qf[d], sd = sf[d];
        float df = sd - qd;
        float u = expf(-df*df);
        su[d] = u;
        S2 += u; M = fmaxf(M, u);
        float sc = 0.25f*cf[d] + 0.5f*sd;
        float d2 = sc - qd;
        S1 += expf(-d2*d2);
    }
    rA[tid]=S1; rB[tid]=S2; rC[tid]=M;
    __syncthreads();
    for (int o=128;o>0;o>>=1){
        if (tid<o){ rA[tid]+=rA[tid+o]; rB[tid]+=rB[tid+o]; rC[tid]=fmaxf(rC[tid],rC[tid+o]); }
        __syncthreads();
    }
    if (tid==0){ sS1 = rA[0]; sS2 = rB[0]; }
    float Mv = rC[0];
    __syncthreads();

    float Se = 0.f;
    for (int d = tid; d < 1024; d += 256) Se += expf(su[d] - Mv);
    rA[tid] = Se;
    __syncthreads();
    for (int o=128;o>0;o>>=1){ if (tid<o) rA[tid]+=rA[tid+o]; __syncthreads(); }
    if (tid==0)
        bmat[q*NSUP + s] = sS1 + sS2 - 1024.f*(Mv + logf(rA[0]));
}

__global__ void dis_kernel(const float* __restrict__ bmat,
                           const int* __restrict__ sy,
                           float* __restrict__ dis)
{
    int q = blockIdx.x;
    __shared__ float row[NSUP];
    __shared__ float red[128];
    int tid = threadIdx.x;
    float m = -1e30f;
    for (int s = tid; s < NSUP; s += 128){ row[s] = bmat[q*NSUP+s]; m = fmaxf(m, row[s]); }
    red[tid] = m; __syncthreads();
    for (int o=64;o>0;o>>=1){ if (tid<o) red[tid]=fmaxf(red[tid],red[tid+o]); __syncthreads(); }
    float mv = red[0]; __syncthreads();
    float se = 0.f;
    for (int s = tid; s < NSUP; s += 128) se += expf(row[s]-mv);
    red[tid] = se; __syncthreads();
    for (int o=64;o>0;o>>=1){ if (tid<o) red[tid]+=red[tid+o]; __syncthreads(); }
    float lse = mv + logf(red[0]);
    if (tid < NCLS){
        float sum = 0.f, cntc = 0.f;
        for (int s=0;s<NSUP;s++) if (sy[s]==tid){ sum += row[s]-lse; cntc += 1.f; }
        dis[q*NCLS+tid] = sum / fmaxf(cntc, 1.f);
    }
}

__global__ void center_kernel(const float* __restrict__ feat,
                              const int* __restrict__ sy,
                              const float* __restrict__ center,
                              float* __restrict__ outp)
{
    int c = blockIdx.x;
    int d = blockIdx.y*256 + threadIdx.x;
    __shared__ int ssy[NSUP];
    for (int s = threadIdx.x; s < NSUP; s += 256) ssy[s] = sy[s];
    __syncthreads();
    float sum = 0.f, cnt = 0.f;
    for (int s=0;s<NSUP;s++) if (ssy[s]==c){ sum += feat[(size_t)s*1024 + d]; cnt += 1.f; }
    outp[c*1024 + d] = (sum/fmaxf(cnt,1.f))*0.5f + 0.25f*center[c*1024 + d];
}

__global__ void loss_kernel(const float* __restrict__ dis,
                            const int* __restrict__ qy,
                            float* __restrict__ outp)
{
    __shared__ float sl[32], sa[32];
    int q = threadIdx.x;
    float l = 0.f, a = 0.f;
    if (q < NQRY){
        const float* r = dis + q*NCLS;
        float best = -1e30f; int arg = 0; float m = -1e30f;
        for (int j=0;j<NCLS;j++){
            float v = r[j];
            if (v > best){ best = v; arg = j; }
            m = fmaxf(m, v);
        }
        float se = 0.f;
        for (int j=0;j<NCLS;j++) se += expf(r[j]-m);
        float lse = m + logf(se);
        int y = qy[q];
        l = lse - r[y];
        a = (arg == y) ? 1.f : 0.f;
    }
    sl[threadIdx.x] = l; sa[threadIdx.x] = a;
    __syncthreads();
    if (threadIdx.x == 0){
        float L=0.f, A=0.f;
        for (int i=0;i<32;i++){ L += sl[i]; A += sa[i]; }
        outp[0] = L; outp[1] = A;
    }
}

// ---------------- host launcher ----------------
extern "C" void kernel_launch(void* const* d_in, const int* in_sizes, int n_in,
                              void* d_out, int out_size)
{
    const float* support_x = (const float*)d_in[0];
    const int*   sup_ei    = (const int*)  d_in[1];
    const int*   sup_y     = (const int*)  d_in[3];
    const float* query_x   = (const float*)d_in[4];
    const int*   qry_ei    = (const int*)  d_in[5];
    const int*   qry_y     = (const int*)  d_in[7];
    const float* center    = (const float*)d_in[8];
    const float* cw1       = (const float*)d_in[9];
    const float* cb1       = (const float*)d_in[10];
    const float* cw_rest   = (const float*)d_in[11];
    const float* cb_rest   = (const float*)d_in[12];
    const float* lin2_w    = (const float*)d_in[13];
    const float* lin2_b    = (const float*)d_in[14];
    const float* mlp_w     = (const float*)d_in[15];
    const float* mlp_b     = (const float*)d_in[16];
    float* out = (float*)d_out;

    int Es = in_sizes[1] / 2;
    int Eq = in_sizes[5] / 2;

    float *buf0, *buf1, *cat, *tmp, *h2, *feat, *agg, *cnt, *bmat, *dis;
    cudaGetSymbolAddress((void**)&buf0, g_buf0);
    cudaGetSymbolAddress((void**)&buf1, g_buf1);
    cudaGetSymbolAddress((void**)&cat,  g_cat);
    cudaGetSymbolAddress((void**)&tmp,  g_tmp);
    cudaGetSymbolAddress((void**)&h2,   g_h2);
    cudaGetSymbolAddress((void**)&feat, g_feat);
    cudaGetSymbolAddress((void**)&agg,  g_agg);
    cudaGetSymbolAddress((void**)&cnt,  g_cnt);
    cudaGetSymbolAddress((void**)&bmat, g_b);
    cudaGetSymbolAddress((void**)&dis,  g_dis);

    const size_t SMEMB = 3*4624*8 + 3*2448*8;  // 169728 bytes
    static int attr_done = 0;
    if (!attr_done){
        cudaFuncSetAttribute(conv64f_kernel<128>, cudaFuncAttributeMaxDynamicSharedMemorySize, (int)SMEMB);
        cudaFuncSetAttribute(conv64f_kernel<64>,  cudaFuncAttributeMaxDynamicSharedMemorySize, (int)SMEMB);
        cudaFuncSetAttribute(conv64f_kernel<32>,  cudaFuncAttributeMaxDynamicSharedMemorySize, (int)SMEMB);
        cudaFuncSetAttribute(conv64f_kernel<16>,  cudaFuncAttributeMaxDynamicSharedMemorySize, (int)SMEMB);
        attr_done = 1;
    }

    const int NG = (NTOT*1024 + 255)/256;
    const int WSTR = 64*64*9;

    // capture slot is launch #4 -> conv64f<128>
    zero_kernel<<<NG,256>>>(agg, NTOT*1024);                                       // #1
    zero_kernel<<<1,256>>>(cnt, NTOT);                                             // #2
    conv1n_kernel<<<dim3(512, NTOT), 512>>>(support_x, query_x, cw1, cb1, buf0);   // #3
    conv64f_kernel<128><<<dim3(64, NTOT), 512, SMEMB>>>(buf0, cw_rest+0*WSTR, cb_rest+0,   buf1, 64*64*64); // #4 captured
    conv64f_kernel< 64><<<dim3(16, NTOT), 512, SMEMB>>>(buf1, cw_rest+1*WSTR, cb_rest+64,  buf0, 64*32*32);
    conv64f_kernel< 32><<<dim3( 4, NTOT), 512, SMEMB>>>(buf0, cw_rest+2*WSTR, cb_rest+128, buf1, 64*16*16);
    conv64f_kernel< 16><<<dim3( 1, NTOT), 512, SMEMB>>>(buf1, cw_rest+3*WSTR, cb_rest+192, buf0, 64*8*8);
    conv64_kernel<8,4><<<dim3( 1, NTOT), 128>>>(buf0, cw_rest+4*WSTR, cb_rest+256, cat, 2048);

    // ---- graph conv 1 ----
    scatter_kernel<<<Es,256>>>(cat, 2048, 0, sup_ei, Es, 0,    agg, cnt);
    scatter_kernel<<<Eq,256>>>(cat, 2048, 0, qry_ei, Eq, NSUP, agg, cnt);
    combine_kernel<<<NG,256>>>(cat, 2048, 0, agg, cnt, tmp, 1024, 0);

    gemm_bias_kernel<<<dim3(16,(NTOT+15)/16),256>>>(tmp, 1024, lin2_w, lin2_b, h2, NTOT, 1024);

    // ---- graph conv 2 ----
    zero_kernel<<<NG,256>>>(agg, NTOT*1024);
    zero_kernel<<<1,256>>>(cnt, NTOT);
    scatter_kernel<<<Es,256>>>(h2, 1024, 0, sup_ei, Es, 0,    agg, cnt);
    scatter_kernel<<<Eq,256>>>(h2, 1024, 0, qry_ei, Eq, NSUP, agg, cnt);
    combine_kernel<<<NG,256>>>(h2, 1024, 0, agg, cnt, cat, 2048, 1024);

    gemm_bias_kernel<<<dim3(16,(NTOT+15)/16),256>>>(cat, 2048, mlp_w, mlp_b, feat, NTOT, 2048);

    pair_kernel<<<dim3(NSUP, NQRY), 256>>>(feat, center, bmat);
    dis_kernel<<<NQRY,128>>>(bmat, sup_y, dis);

    center_kernel<<<dim3(NCLS,4),256>>>(feat, sup_y, center, out + 2);
    loss_kernel<<<1,32>>>(dis, qry_y, out);
}

// round 10
// speedup vs baseline: 1.0481x; 1.0481x over previous
#include <cuda_runtime.h>
#include <math.h>

typedef unsigned long long u64;

// ---------------- problem constants ----------------
static const int NSUP  = 115;
static const int NQRY  = 23;
static const int NTOT  = 138;
static const int NCLS  = 23;

// ---------------- device scratch ----------------
__device__ float g_buf0[(size_t)NTOT*64*128*128];
__device__ float g_buf1[(size_t)NTOT*64*64*64];
__device__ __align__(16) u64 g_wdup2[4*8*4624];   // padded dup weights [layer][chunk][4624]
__device__ float g_cat [(size_t)NTOT*2048];
__device__ float g_tmp [(size_t)NTOT*1024];
__device__ float g_h2  [(size_t)NTOT*1024];
__device__ float g_feat[(size_t)NTOT*1024];
__device__ float g_agg [(size_t)NTOT*1024];
__device__ float g_cnt [NTOT];
__device__ float g_b   [NQRY*NSUP];
__device__ float g_dis [NQRY*NCLS];

// ---------------- packed f32x2 helpers ----------------
__device__ __forceinline__ u64 pk2(float x, float y){
    u64 r; asm("mov.b64 %0, {%1, %2};" : "=l"(r) : "f"(x), "f"(y)); return r;
}
__device__ __forceinline__ void fma2(u64 &d, u64 a, u64 b){
    asm("fma.rn.f32x2 %0, %1, %2, %0;" : "+l"(d) : "l"(a), "l"(b));
}
__device__ __forceinline__ float2 up2(u64 a){
    float2 r; asm("mov.b64 {%0, %1}, %2;" : "=f"(r.x), "=f"(r.y) : "l"(a)); return r;
}
__device__ __forceinline__ u64 cmp2(u64 a, u64 b){ return (a >> 32) | (b << 32); }

// ---------------- prep: padded duplicated weights for conv2..5 ----------------
__global__ void wdup2_kernel(const float* __restrict__ cwr, u64* __restrict__ wd)
{
    int i = blockIdx.x*256 + threadIdx.x;
    if (i >= 4*8*4608) return;
    int L = i / (8*4608);
    int r = i % (8*4608);
    int chunk = r / 4608;
    int we = r % 4608;
    int oc = we/72; int rem = we - oc*72; int k = rem/9; int t = rem - k*9;
    float v = cwr[(size_t)L*36864 + (oc*64 + chunk*8 + k)*9 + t];
    wd[((size_t)L*8 + chunk)*4624 + we + we/288] = pk2(v, v);
}

// ---------------- conv1n: 3->64, weights-in-registers, 2 CTAs/SM (proven) ----------------
__global__ void __launch_bounds__(512, 2)
conv1n_kernel(const float* __restrict__ sx,
              const float* __restrict__ qx,
              const float* __restrict__ w,
              const float* __restrict__ bias,
              float* __restrict__ out)
{
    __shared__ __align__(16) float sTile[3][10][18];
    __shared__ u64 sW[64][27];

    const int tid = threadIdx.x;
    const int img = blockIdx.y;
    const int tx = blockIdx.x & 15;
    const int ty = blockIdx.x >> 4;
    const int gx0 = tx*16, gy0 = ty*8;
    const float* inImg = (img < NSUP) ? sx + (size_t)img*3*65536
                                      : qx + (size_t)(img-NSUP)*3*65536;

    for (int idx = tid; idx < 540; idx += 512){
        int k = idx/180; int rem = idx - k*180;
        int r = rem/18, c = rem - r*18;
        int iy = gy0 - 1 + r, ix = gx0 - 1 + c;
        float v = 0.f;
        if ((unsigned)iy < 256u && (unsigned)ix < 256u)
            v = inImg[k*65536 + iy*256 + ix];
        sTile[k][r][c] = v;
    }
    for (int idx = tid; idx < 1728; idx += 512){
        float v = w[idx];
        sW[idx/27][idx%27] = pk2(v, v);
    }
    __syncthreads();

    const int oc  = tid >> 3;
    const int sid = tid & 7;
    const u64* tbase = (const u64*)sTile;

    u64 acc[8];
    #pragma unroll
    for (int r = 0; r < 8; r++) acc[r] = 0ull;

    #pragma unroll
    for (int ci = 0; ci < 3; ci++){
        u64 wr[9];
        #pragma unroll
        for (int t = 0; t < 9; t++) wr[t] = sW[oc][ci*9 + t];
        #pragma unroll
        for (int tr = 0; tr < 10; tr++){
            u64 T0 = tbase[(ci*10 + tr)*9 + sid];
            u64 T2 = tbase[(ci*10 + tr)*9 + sid + 1];
            u64 T1 = cmp2(T0, T2);
            #pragma unroll
            for (int dy = 0; dy < 3; dy++){
                const int r = tr - dy;
                if (r >= 0 && r < 8){
                    fma2(acc[r], T0, wr[dy*3+0]);
                    fma2(acc[r], T1, wr[dy*3+1]);
                    fma2(acc[r], T2, wr[dy*3+2]);
                }
            }
        }
    }

    float b = bias[oc];
    const int pxl = tx*8 + sid;
    const int py0 = ty*4;
    float* op = out + ((size_t)img*64 + oc)*16384;
    #pragma unroll
    for (int i = 0; i < 4; i++){
        float2 a0 = up2(acc[2*i]), a1 = up2(acc[2*i+1]);
        float m = fmaxf(fmaxf(a0.x, a0.y), fmaxf(a1.x, a1.y)) + b;
        op[(py0 + i)*128 + pxl] = fmaxf(m, 0.f);
    }
}

// ---------------- conv64g: 256 thr, warp = 2 ocg x 16 pos, bank-exact, 2 CTAs/SM ----------------
// tile 16 conv cols x 8 conv rows; pos: px=pos>>1 (0..7), pr=pos&1 (0..1)
// sPk rows padded to 18 u64; sW ocg blocks padded to 289 u64
template<int IN_H>
__global__ void __launch_bounds__(256,2)
conv64g_kernel(const float* __restrict__ in,
               const u64*  __restrict__ wdup,    // per-layer [8][4624]
               const float* __restrict__ bias,
               float* __restrict__ out,
               int outImgStride)
{
    constexpr int PH   = IN_H/2;
    constexpr int TX   = PH/8;
    constexpr int CHUNK= 8;
    constexpr int HH   = IN_H*IN_H;
    constexpr int RSTR = 18;
    constexpr int PKN  = CHUNK*10*RSTR;   // 1440
    constexpr int PKL  = CHUNK*10*17;     // 1360 logical entries
    constexpr int WNP  = 4624;

    extern __shared__ __align__(16) unsigned char sm[];
    u64* sW  = (u64*)sm;                          // [2][WNP]
    u64* sPk = (u64*)(sm + 2*(size_t)WNP*8);      // [2][PKN]

    const int tid = threadIdx.x;
    const int ocg = tid >> 4;      // 0..15
    const int pos = tid & 15;
    const int px  = pos >> 1;      // 0..7
    const int pr  = pos & 1;       // 0..1
    const int img = blockIdx.y;
    const int tpy = blockIdx.x / TX, tpx = blockIdx.x % TX;
    const int cy0 = tpy*8, cx0 = tpx*16;
    const float* inImg = in + (size_t)img*64*HH;

    // producer precompute (input only; weights are linear copies)
    int eoff[6], sdst[6]; bool ep0[6], ep1[6];
    #pragma unroll
    for (int j=0;j<6;j++){
        int e = tid + j*256;
        bool v = e < PKL;
        int ee = v ? e : 0;
        int k = ee/170, rem = ee - k*170;
        int r = rem/17,  s  = rem - r*17;
        int c0 = (s<9) ? 2*s : 2*(s-9)+1;
        int iy = cy0-1+r, ix0 = cx0-1+c0;
        bool rowok = (unsigned)iy < (unsigned)IN_H;
        ep0[j] = v && rowok && (unsigned)ix0     < (unsigned)IN_H;
        ep1[j] = v && rowok && (unsigned)(ix0+1) < (unsigned)IN_H;
        eoff[j] = k*HH + iy*IN_H + ix0;
        sdst[j] = (k*10 + r)*RSTR + s;
    }

    u64 acc[4][4];
    #pragma unroll
    for (int o=0;o<4;o++)
        #pragma unroll
        for (int cc=0;cc<4;cc++) acc[o][cc] = 0ull;

    float f[6][2];
    const float* pIn = inImg;
    const u64*   pWg = wdup;

    // ---- prologue: chunk0 input staged+stored, weights chunk0 copied, chunk1 input staged ----
    #pragma unroll
    for (int j=0;j<6;j++){
        f[j][0] = ep0[j] ? pIn[eoff[j]]   : 0.f;
        f[j][1] = ep1[j] ? pIn[eoff[j]+1] : 0.f;
    }
    pIn += CHUNK*HH;
    #pragma unroll
    for (int j=0;j<6;j++)
        if (ep0[j] | ep1[j] | (tid + j*256 < PKL))
            { int e = tid + j*256; if (e < PKL) *(float2*)(sPk + sdst[j]) = make_float2(f[j][0], f[j][1]); }
    #pragma unroll
    for (int j=0;j<19;j++){
        int e = tid + j*256;
        if (e < WNP) sW[e] = pWg[e];
    }
    pWg += WNP;
    #pragma unroll
    for (int j=0;j<6;j++){
        f[j][0] = ep0[j] ? pIn[eoff[j]]   : 0.f;
        f[j][1] = ep1[j] ? pIn[eoff[j]+1] : 0.f;
    }
    pIn += CHUNK*HH;
    __syncthreads();

    int rb = 0;
    #pragma unroll 1
    for (int c = 0; c < 8; c++){
        // FMA on rb
        const u64* pkb = sPk + rb*PKN;
        const u64* wbb = sW  + rb*WNP + ocg*289;
        #pragma unroll
        for (int k=0;k<CHUNK;k++){
            const u64* prow = pkb + (k*10 + 4*pr)*RSTR;
            u64 P[6][3];
            #pragma unroll
            for (int r=0;r<6;r++){
                P[r][0] = prow[r*RSTR + px];
                P[r][1] = prow[r*RSTR + 9 + px];
                P[r][2] = prow[r*RSTR + px + 1];
            }
            #pragma unroll
            for (int o=0;o<4;o++){
                const u64* wp = wbb + (o*8 + k)*9;
                #pragma unroll
                for (int dy=0;dy<3;dy++){
                    u64 w0 = wp[dy*3+0], w1 = wp[dy*3+1], w2 = wp[dy*3+2];
                    #pragma unroll
                    for (int cc=0;cc<4;cc++) fma2(acc[o][cc], P[cc+dy][0], w0);
                    #pragma unroll
                    for (int cc=0;cc<4;cc++) fma2(acc[o][cc], P[cc+dy][1], w1);
                    #pragma unroll
                    for (int cc=0;cc<4;cc++) fma2(acc[o][cc], P[cc+dy][2], w2);
                }
            }
        }

        if (c == 7) break;
        __syncthreads();

        // store staged input chunk c+1 and copy weights chunk c+1 into rb^1
        {
            u64* pkw = sPk + (rb^1)*PKN;
            u64* ww  = sW  + (rb^1)*WNP;
            #pragma unroll
            for (int j=0;j<6;j++){
                int e = tid + j*256;
                if (e < PKL) *(float2*)(pkw + sdst[j]) = make_float2(f[j][0], f[j][1]);
            }
            #pragma unroll
            for (int j=0;j<19;j++){
                int e = tid + j*256;
                if (e < WNP) ww[e] = pWg[e];
            }
            pWg += WNP;
        }
        // stage input chunk c+2
        if (c < 6){
            #pragma unroll
            for (int j=0;j<6;j++){
                f[j][0] = ep0[j] ? pIn[eoff[j]]   : 0.f;
                f[j][1] = ep1[j] ? pIn[eoff[j]+1] : 0.f;
            }
            pIn += CHUNK*HH;
        }
        __syncthreads();
        rb ^= 1;
    }

    // epilogue: pool 2x2, bias, relu
    const int gx  = tpx*8 + px;
    const int gy0 = tpy*4 + 2*pr;
    #pragma unroll
    for (int o=0;o<4;o++){
        int oc = ocg*4 + o;
        float b = bias[oc];
        float2 a0 = up2(acc[o][0]), a1 = up2(acc[o][1]);
        float2 a2 = up2(acc[o][2]), a3 = up2(acc[o][3]);
        float m0 = fmaxf(fmaxf(a0.x,a0.y), fmaxf(a1.x,a1.y)) + b; m0 = fmaxf(m0, 0.f);
        float m1 = fmaxf(fmaxf(a2.x,a2.y), fmaxf(a3.x,a3.y)) + b; m1 = fmaxf(m1, 0.f);
        float* op = out + (size_t)img*outImgStride + (size_t)oc*PH*PH;
        op[(size_t)gy0*PH + gx]     = m0;
        op[(size_t)(gy0+1)*PH + gx] = m1;
    }
}

// ---------------- conv6 (proven conv64_kernel<8,4>) ----------------
template<int IN_H, int TILE_P>
__global__ void conv64_kernel(const float* __restrict__ in,
                              const float* __restrict__ w,
                              const float* __restrict__ bias,
                              float* __restrict__ out,
                              int outImgStride)
{
    constexpr int PH    = IN_H/2;
    constexpr int TILES = PH / TILE_P;
    constexpr int TI    = TILE_P*2 + 2;
    constexpr int POS   = TILE_P*TILE_P;
    constexpr int NT    = POS*8;
    constexpr int CHUNK = 8;

    __shared__ __align__(16) float sIn[CHUNK][TI][TI];
    __shared__ u64 sW[64][CHUNK][9];

    const int tid = threadIdx.x;
    const int pos = tid & (POS-1);
    const int ocg = tid / POS;
    const int py = pos / TILE_P, px = pos % TILE_P;
    const int img = blockIdx.y;
    const int tpy = blockIdx.x / TILES, tpx = blockIdx.x % TILES;
    const int cy0 = tpy*TILE_P*2, cx0 = tpx*TILE_P*2;
    const float* inImg = in + (size_t)img*64*IN_H*IN_H;

    u64 accA[8], accB[8];
    #pragma unroll
    for (int i=0;i<8;i++){ accA[i]=0ull; accB[i]=0ull; }

    for (int ci0 = 0; ci0 < 64; ci0 += CHUNK){
        for (int idx = tid; idx < CHUNK*TI*TI; idx += NT){
            int k = idx/(TI*TI), rem = idx%(TI*TI);
            int r = rem/TI, c = rem%TI;
            int iy = cy0-1+r, ix = cx0-1+c;
            float v = 0.f;
            if (iy>=0 && iy<IN_H && ix>=0 && ix<IN_H)
                v = inImg[(size_t)(ci0+k)*IN_H*IN_H + (size_t)iy*IN_H + ix];
            sIn[k][r][c] = v;
        }
        for (int idx = tid; idx < 64*CHUNK*9; idx += NT){
            int oc = idx/(CHUNK*9), rem = idx%(CHUNK*9);
            int k = rem/9, t = rem%9;
            float wv = w[(oc*64 + (ci0+k))*9 + t];
            sW[oc][k][t] = pk2(wv, wv);
        }
        __syncthreads();

        #pragma unroll
        for (int k=0;k<CHUNK;k++){
            u64 P[4][3];
            #pragma unroll
            for (int r=0;r<4;r++){
                float2 a = *(const float2*)&sIn[k][2*py+r][2*px];
                float2 b = *(const float2*)&sIn[k][2*py+r][2*px+2];
                P[r][0] = pk2(a.x, a.y);
                P[r][1] = pk2(a.y, b.x);
                P[r][2] = pk2(b.x, b.y);
            }
            #pragma unroll
            for (int o=0;o<8;o++){
                const u64* wp = &sW[ocg*8+o][k][0];
                #pragma unroll
                for (int dy=0;dy<3;dy++){
                    #pragma unroll
                    for (int dx=0;dx<3;dx++){
                        u64 wv = wp[dy*3+dx];
                        fma2(accA[o], P[dy][dx],   wv);
                        fma2(accB[o], P[dy+1][dx], wv);
                    }
                }
            }
        }
        __syncthreads();
    }

    const int gy = tpy*TILE_P+py, gx = tpx*TILE_P+px;
    #pragma unroll
    for (int o=0;o<8;o++){
        int oc = ocg*8+o;
        float2 ca = up2(accA[o]); float2 cb = up2(accB[o]);
        float m = fmaxf(fmaxf(ca.x,ca.y), fmaxf(cb.x,cb.y)) + bias[oc];
        m = fmaxf(m, 0.f);
        out[(size_t)img*outImgStride + (size_t)oc*PH*PH + (size_t)gy*PH + gx] = m;
    }
}

// ---------------- small kernels (proven) ----------------
__global__ void zero_kernel(float* __restrict__ p, int n){
    int i = blockIdx.x*256 + threadIdx.x;
    if (i < n) p[i] = 0.f;
}

__global__ void scatter_kernel(const float* __restrict__ feat, int stride, int colOff,
                               const int* __restrict__ ei, int E, int base,
                               float* __restrict__ agg, float* __restrict__ cnt)
{
    int e = blockIdx.x;
    int src = ei[e], dst = ei[E + e];
    const float* f = feat + (size_t)(base+src)*stride + colOff;
    float* a = agg + (size_t)(base+dst)*1024;
    for (int d = threadIdx.x; d < 1024; d += blockDim.x)
        atomicAdd(&a[d], f[d]);
    if (threadIdx.x == 0) atomicAdd(&cnt[base+dst], 1.f);
}

__global__ void combine_kernel(const float* __restrict__ feat, int fstride, int fcolOff,
                               const float* __restrict__ agg, const float* __restrict__ cnt,
                               float* __restrict__ outp, int ostride, int ocolOff)
{
    int i = blockIdx.x*256 + threadIdx.x;
    if (i >= NTOT*1024) return;
    int n = i >> 10, d = i & 1023;
    float c = fmaxf(cnt[n], 1.f);
    float fv = feat[(size_t)n*fstride + fcolOff + d];
    outp[(size_t)n*ostride + ocolOff + d] = (agg[i]/c) * fv;
}

__global__ void gemm_bias_kernel(const float* __restrict__ A, int lda,
                                 const float* __restrict__ W,
                                 const float* __restrict__ bias,
                                 float* __restrict__ C, int M, int K)
{
    __shared__ float sA[16][17];
    __shared__ float sB[16][64];
    int tx = threadIdx.x & 15, ty = threadIdx.x >> 4;
    int n0 = blockIdx.x*64, m0 = blockIdx.y*16;
    float acc[4] = {0.f,0.f,0.f,0.f};
    for (int k0 = 0; k0 < K; k0 += 16){
        int m = m0 + ty;
        sA[ty][tx] = (m < M) ? A[(size_t)m*lda + k0 + tx] : 0.f;
        #pragma unroll
        for (int j=0;j<4;j++)
            sB[ty][tx*4+j] = W[(size_t)(k0+ty)*1024 + n0 + tx*4 + j];
        __syncthreads();
        #pragma unroll
        for (int kk=0;kk<16;kk++){
            float a = sA[ty][kk];
            #pragma unroll
            for (int j=0;j<4;j++) acc[j] += a * sB[kk][tx*4+j];
        }
        __syncthreads();
    }
    int m = m0 + ty;
    if (m < M){
        #pragma unroll
        for (int j=0;j<4;j++)
            C[(size_t)m*1024 + n0 + tx*4 + j] = acc[j] + bias[n0 + tx*4 + j];
    }
}

__global__ void pair_kernel(const float* __restrict__ feat,
                            const float* __restrict__ center,
                            float* __restrict__ bmat)
{
    int s = blockIdx.x, q = blockIdx.y;
    const float* qf = feat + (size_t)(NSUP+q)*1024;
    const float* sf = feat + (size_t)s*1024;
    const float* cf = center + (size_t)(s/5)*1024;
    __shared__ float su[1024];
    __shared__ float rA[256], rB[256], rC[256];
    __shared__ float sS1, sS2;
    int tid = threadIdx.x;

    float S1 = 0.f, S2 = 0.f, M = -1e30f;
    for (int d = tid; d < 1024; d += 256){
        float qd = qf[d], sd = sf[d];
        float df = sd - qd;
        float u = expf(-df*df);
        su[d] = u;
        S2 += u; M = fmaxf(M, u);
        float sc = 0.25f*cf[d] + 0.5f*sd;
        float d2 = sc - qd;
        S1 += expf(-d2*d2);
    }
    rA[tid]=S1; rB[tid]=S2; rC[tid]=M;
    __syncthreads();
    for (int o=128;o>0;o>>=1){
        if (tid<o){ rA[tid]+=rA[tid+o]; rB[tid]+=rB[tid+o]; rC[tid]=fmaxf(rC[tid],rC[tid+o]); }
        __syncthreads();
    }
    if (tid==0){ sS1 = rA[0]; sS2 = rB[0]; }
    float Mv = rC[0];
    __syncthreads();

    float Se = 0.f;
    for (int d = tid; d < 1024; d += 256) Se += expf(su[d] - Mv);
    rA[tid] = Se;
    __syncthreads();
    for (int o=128;o>0;o>>=1){ if (tid<o) rA[tid]+=rA[tid+o]; __syncthreads(); }
    if (tid==0)
        bmat[q*NSUP + s] = sS1 + sS2 - 1024.f*(Mv + logf(rA[0]));
}

__global__ void dis_kernel(const float* __restrict__ bmat,
                           const int* __restrict__ sy,
                           float* __restrict__ dis)
{
    int q = blockIdx.x;
    __shared__ float row[NSUP];
    __shared__ float red[128];
    int tid = threadIdx.x;
    float m = -1e30f;
    for (int s = tid; s < NSUP; s += 128){ row[s] = bmat[q*NSUP+s]; m = fmaxf(m, row[s]); }
    red[tid] = m; __syncthreads();
    for (int o=64;o>0;o>>=1){ if (tid<o) red[tid]=fmaxf(red[tid],red[tid+o]); __syncthreads(); }
    float mv = red[0]; __syncthreads();
    float se = 0.f;
    for (int s = tid; s < NSUP; s += 128) se += expf(row[s]-mv);
    red[tid] = se; __syncthreads();
    for (int o=64;o>0;o>>=1){ if (tid<o) red[tid]+=red[tid+o]; __syncthreads(); }
    float lse = mv + logf(red[0]);
    if (tid < NCLS){
        float sum = 0.f, cntc = 0.f;
        for (int s=0;s<NSUP;s++) if (sy[s]==tid){ sum += row[s]-lse; cntc += 1.f; }
        dis[q*NCLS+tid] = sum / fmaxf(cntc, 1.f);
    }
}

__global__ void center_kernel(const float* __restrict__ feat,
                              const int* __restrict__ sy,
                              const float* __restrict__ center,
                              float* __restrict__ outp)
{
    int c = blockIdx.x;
    int d = blockIdx.y*256 + threadIdx.x;
    __shared__ int ssy[NSUP];
    for (int s = threadIdx.x; s < NSUP; s += 256) ssy[s] = sy[s];
    __syncthreads();
    float sum = 0.f, cnt = 0.f;
    for (int s=0;s<NSUP;s++) if (ssy[s]==c){ sum += feat[(size_t)s*1024 + d]; cnt += 1.f; }
    outp[c*1024 + d] = (sum/fmaxf(cnt,1.f))*0.5f + 0.25f*center[c*1024 + d];
}

__global__ void loss_kernel(const float* __restrict__ dis,
                            const int* __restrict__ qy,
                            float* __restrict__ outp)
{
    __shared__ float sl[32], sa[32];
    int q = threadIdx.x;
    float l = 0.f, a = 0.f;
    if (q < NQRY){
        const float* r = dis + q*NCLS;
        float best = -1e30f; int arg = 0; float m = -1e30f;
        for (int j=0;j<NCLS;j++){
            float v = r[j];
            if (v > best){ best = v; arg = j; }
            m = fmaxf(m, v);
        }
        float se = 0.f;
        for (int j=0;j<NCLS;j++) se += expf(r[j]-m);
        float lse = m + logf(se);
        int y = qy[q];
        l = lse - r[y];
        a = (arg == y) ? 1.f : 0.f;
    }
    sl[threadIdx.x] = l; sa[threadIdx.x] = a;
    __syncthreads();
    if (threadIdx.x == 0){
        float L=0.f, A=0.f;
        for (int i=0;i<32;i++){ L += sl[i]; A += sa[i]; }
        outp[0] = L; outp[1] = A;
    }
}

// ---------------- host launcher ----------------
extern "C" void kernel_launch(void* const* d_in, const int* in_sizes, int n_in,
                              void* d_out, int out_size)
{
    const float* support_x = (const float*)d_in[0];
    const int*   sup_ei    = (const int*)  d_in[1];
    const int*   sup_y     = (const int*)  d_in[3];
    const float* query_x   = (const float*)d_in[4];
    const int*   qry_ei    = (const int*)  d_in[5];
    const int*   qry_y     = (const int*)  d_in[7];
    const float* center    = (const float*)d_in[8];
    const float* cw1       = (const float*)d_in[9];
    const float* cb1       = (const float*)d_in[10];
    const float* cw_rest   = (const float*)d_in[11];
    const float* cb_rest   = (const float*)d_in[12];
    const float* lin2_w    = (const float*)d_in[13];
    const float* lin2_b    = (const float*)d_in[14];
    const float* mlp_w     = (const float*)d_in[15];
    const float* mlp_b     = (const float*)d_in[16];
    float* out = (float*)d_out;

    int Es = in_sizes[1] / 2;
    int Eq = in_sizes[5] / 2;

    float *buf0, *buf1, *cat, *tmp, *h2, *feat, *agg, *cnt, *bmat, *dis;
    u64* wdup;
    cudaGetSymbolAddress((void**)&buf0, g_buf0);
    cudaGetSymbolAddress((void**)&buf1, g_buf1);
    cudaGetSymbolAddress((void**)&wdup, g_wdup2);
    cudaGetSymbolAddress((void**)&cat,  g_cat);
    cudaGetSymbolAddress((void**)&tmp,  g_tmp);
    cudaGetSymbolAddress((void**)&h2,   g_h2);
    cudaGetSymbolAddress((void**)&feat, g_feat);
    cudaGetSymbolAddress((void**)&agg,  g_agg);
    cudaGetSymbolAddress((void**)&cnt,  g_cnt);
    cudaGetSymbolAddress((void**)&bmat, g_b);
    cudaGetSymbolAddress((void**)&dis,  g_dis);

    const size_t SMEMG = 2*(4624 + 1440)*8;   // 97024 bytes
    static int attr_done = 0;
    if (!attr_done){
        cudaFuncSetAttribute(conv64g_kernel<128>, cudaFuncAttributeMaxDynamicSharedMemorySize, (int)SMEMG);
        cudaFuncSetAttribute(conv64g_kernel<64>,  cudaFuncAttributeMaxDynamicSharedMemorySize, (int)SMEMG);
        cudaFuncSetAttribute(conv64g_kernel<32>,  cudaFuncAttributeMaxDynamicSharedMemorySize, (int)SMEMG);
        cudaFuncSetAttribute(conv64g_kernel<16>,  cudaFuncAttributeMaxDynamicSharedMemorySize, (int)SMEMG);
        attr_done = 1;
    }

    const int NG = (NTOT*1024 + 255)/256;
    const int LW = 8*4624;   // per-layer stride in g_wdup2

    // capture slot = launch #4 -> conv64g<128>
    wdup2_kernel<<<(4*8*4608 + 255)/256, 256>>>(cw_rest, wdup);                    // #1
    zero_kernel<<<NG,256>>>(agg, NTOT*1024);                                       // #2
    conv1n_kernel<<<dim3(512, NTOT), 512>>>(support_x, query_x, cw1, cb1, buf0);   // #3
    conv64g_kernel<128><<<dim3(128, NTOT), 256, SMEMG>>>(buf0, wdup + 0*LW, cb_rest+0,   buf1, 64*64*64); // #4
    conv64g_kernel< 64><<<dim3( 32, NTOT), 256, SMEMG>>>(buf1, wdup + 1*LW, cb_rest+64,  buf0, 64*32*32);
    conv64g_kernel< 32><<<dim3(  8, NTOT), 256, SMEMG>>>(buf0, wdup + 2*LW, cb_rest+128, buf1, 64*16*16);
    conv64g_kernel< 16><<<dim3(  2, NTOT), 256, SMEMG>>>(buf1, wdup + 3*LW, cb_rest+192, buf0, 64*8*8);
    conv64_kernel<8,4><<<dim3( 1, NTOT), 128>>>(buf0, cw_rest + 4*(64*64*9), cb_rest + 256, cat, 2048);

    zero_kernel<<<1,256>>>(cnt, NTOT);

    // ---- graph conv 1 ----
    scatter_kernel<<<Es,256>>>(cat, 2048, 0, sup_ei, Es, 0,    agg, cnt);
    scatter_kernel<<<Eq,256>>>(cat, 2048, 0, qry_ei, Eq, NSUP, agg, cnt);
    combine_kernel<<<NG,256>>>(cat, 2048, 0, agg, cnt, tmp, 1024, 0);

    gemm_bias_kernel<<<dim3(16,(NTOT+15)/16),256>>>(tmp, 1024, lin2_w, lin2_b, h2, NTOT, 1024);

    // ---- graph conv 2 ----
    zero_kernel<<<NG,256>>>(agg, NTOT*1024);
    zero_kernel<<<1,256>>>(cnt, NTOT);
    scatter_kernel<<<Es,256>>>(h2, 1024, 0, sup_ei, Es, 0,    agg, cnt);
    scatter_kernel<<<Eq,256>>>(h2, 1024, 0, qry_ei, Eq, NSUP, agg, cnt);
    combine_kernel<<<NG,256>>>(h2, 1024, 0, agg, cnt, cat, 2048, 1024);

    gemm_bias_kernel<<<dim3(16,(NTOT+15)/16),256>>>(cat, 2048, mlp_w, mlp_b, feat, NTOT, 2048);

    pair_kernel<<<dim3(NSUP, NQRY), 256>>>(feat, center, bmat);
    dis_kernel<<<NQRY,128>>>(bmat, sup_y, dis);

    center_kernel<<<dim3(NCLS,4),256>>>(feat, sup_y, center, out + 2);
    loss_kernel<<<1,32>>>(dis, qry_y, out);
}

// round 13
// speedup vs baseline: 1.3745x; 1.3114x over previous
#include <cuda_runtime.h>
#include <cuda_bf16.h>
#include <math.h>

typedef unsigned long long u64;
typedef unsigned int u32;

// ---------------- problem constants ----------------
static const int NSUP  = 115;
static const int NQRY  = 23;
static const int NTOT  = 138;
static const int NCLS  = 23;

// ---------------- device scratch ----------------
__device__ float g_buf0[(size_t)NTOT*64*128*128];
__device__ float g_buf1[(size_t)NTOT*64*64*64];
__device__ __nv_bfloat16 g_ahi[(size_t)NTOT*128*130*64];   // conv1 out transposed, hi part
__device__ __nv_bfloat16 g_alo[(size_t)NTOT*128*130*64];   // lo part
__device__ __nv_bfloat16 g_wb [18*64*64];                  // conv2 weights [tp][ci(k)][oc]
__device__ float g_cat [(size_t)NTOT*2048];
__device__ float g_tmp [(size_t)NTOT*1024];
__device__ float g_h2  [(size_t)NTOT*1024];
__device__ float g_feat[(size_t)NTOT*1024];
__device__ float g_agg [(size_t)NTOT*1024];
__device__ float g_cnt [NTOT];
__device__ float g_b   [NQRY*NSUP];
__device__ float g_dis [NQRY*NCLS];

// ---------------- packed f32x2 helpers ----------------
__device__ __forceinline__ u64 pk2(float x, float y){
    u64 r; asm("mov.b64 %0, {%1, %2};" : "=l"(r) : "f"(x), "f"(y)); return r;
}
__device__ __forceinline__ void fma2(u64 &d, u64 a, u64 b){
    asm("fma.rn.f32x2 %0, %1, %2, %0;" : "+l"(d) : "l"(a), "l"(b));
}
__device__ __forceinline__ float2 up2(u64 a){
    float2 r; asm("mov.b64 {%0, %1}, %2;" : "=f"(r.x), "=f"(r.y) : "l"(a)); return r;
}
__device__ __forceinline__ u64 cmp2(u64 a, u64 b){ return (a >> 32) | (b << 32); }

// ---------------- warp-mma helpers (sm_80+) ----------------
__device__ __forceinline__ void ldsm4(u32* r, u32 addr){
    asm volatile("ldmatrix.sync.aligned.m8n8.x4.shared.b16 {%0,%1,%2,%3}, [%4];"
        : "=r"(r[0]),"=r"(r[1]),"=r"(r[2]),"=r"(r[3]) : "r"(addr));
}
__device__ __forceinline__ void ldsm4t(u32* r, u32 addr){
    asm volatile("ldmatrix.sync.aligned.m8n8.x4.trans.shared.b16 {%0,%1,%2,%3}, [%4];"
        : "=r"(r[0]),"=r"(r[1]),"=r"(r[2]),"=r"(r[3]) : "r"(addr));
}
#define MMA(dd, a, b0, b1) \
    asm volatile("mma.sync.aligned.m16n8k16.row.col.f32.bf16.bf16.f32 " \
        "{%0,%1,%2,%3},{%4,%5,%6,%7},{%8,%9},{%0,%1,%2,%3};" \
        : "+f"((dd)[0]),"+f"((dd)[1]),"+f"((dd)[2]),"+f"((dd)[3]) \
        : "r"((a)[0]),"r"((a)[1]),"r"((a)[2]),"r"((a)[3]), "r"(b0),"r"(b1))

// ---------------- prep: conv2 weight split, layout [tp][ci(k)][oc] ----------------
__global__ void wb2_kernel(const float* __restrict__ cwr, __nv_bfloat16* __restrict__ wbp)
{
    int i = blockIdx.x*256 + threadIdx.x;          // over 18*64*64
    if (i >= 73728) return;
    int oc = i & 63, ci = (i>>6)&63, tp = i>>12;   // tp = tap*2 + part
    int tap = tp >> 1, part = tp & 1;
    float v = cwr[(oc*64 + ci)*9 + tap];
    __nv_bfloat16 h = __float2bfloat16(v);
    wbp[i] = (part == 0) ? h : __float2bfloat16(v - __bfloat162float(h));
}

// ---------------- prep: transpose conv1 out to [img][y][x+1][ci] bf16 hi/lo ----------------
__global__ void tr_kernel(const float* __restrict__ in,
                          __nv_bfloat16* __restrict__ ahi,
                          __nv_bfloat16* __restrict__ alo)
{
    __shared__ float sT[64][133];
    int y = blockIdx.x, img = blockIdx.y;
    const float* src = in + (size_t)img*64*16384 + y*128;
    for (int e = threadIdx.x; e < 64*130; e += 256){
        int ci = e / 130, xi = e - ci*130;
        int xs = xi - 1;
        float v = ((unsigned)xs < 128u) ? src[(size_t)ci*16384 + xs] : 0.f;
        sT[ci][xi] = v;
    }
    __syncthreads();
    size_t ob = (size_t)(img*128 + y)*130*64;
    for (int e = threadIdx.x; e < 130*64; e += 256){
        int xi = e >> 6, ci = e & 63;
        float v = sT[ci][xi];
        __nv_bfloat16 h = __float2bfloat16(v);
        ahi[ob + e] = h;
        alo[ob + e] = __float2bfloat16(v - __bfloat162float(h));
    }
}

// ---------------- tconv2m: conv2 via warp mma.sync, split-bf16 (fixed B layout) ----------------
// grid (2 halves, 138 imgs), 256 thr = 8 warps; warp = 16 x-positions x 32 oc.
// smem: B [18 tp][64 k][80B] = 92160 | A ring 2 parts x 3 slots x (130 x 144B) = 112320 | bias 128
__global__ void __launch_bounds__(256,1)
tconv2m_kernel(const __nv_bfloat16* __restrict__ ahi,
               const __nv_bfloat16* __restrict__ alo,
               const __nv_bfloat16* __restrict__ wbp,
               const float* __restrict__ bias,
               float* __restrict__ out)
{
    extern __shared__ __align__(16) unsigned char sm[];
    const u32 SB = (u32)__cvta_generic_to_shared(sm);
    const u32 SMB   = 0;
    const u32 SMA   = 92160;            // 18*5120
    const u32 SLOT  = 18720;            // 130*144
    const u32 APART = 3*18720;          // 56160
    float* sBias = (float*)(sm + SMA + 2*APART);

    const int tid  = threadIdx.x;
    const int warp = tid >> 5;
    const int t    = tid & 31;
    const int half = blockIdx.x;
    const int img  = blockIdx.y;
    const int m0   = warp*16;

    // ---- load B: per tp tile [64 k][32 oc], row stride 80B ----
    const u32* wb32 = (const u32*)wbp;
    for (int e = tid; e < 18432; e += 256){
        int oc2 = e & 15, ci = (e>>4)&63, tp = e>>10;
        u32 v = wb32[(tp*64 + ci)*32 + half*16 + oc2];
        *(u32*)(sm + SMB + (u32)tp*5120 + (u32)ci*80 + (u32)oc2*4) = v;
    }
    if (tid < 32) sBias[tid] = bias[half*32 + tid];

    const u32* srcH = (const u32*)(ahi + (size_t)img*128*130*64);
    const u32* srcL = (const u32*)(alo + (size_t)img*128*130*64);

    auto load_row = [&](int j){
        if ((unsigned)j >= 128u) return;
        u32 slotB = SMA + (u32)((j+1)%3)*SLOT;
        const u32* sh = srcH + (size_t)j*4160;
        const u32* sl = srcL + (size_t)j*4160;
        for (int e = tid; e < 4160; e += 256){
            int xi = e >> 5, ci2 = e & 31;
            u32 off = slotB + (u32)xi*144 + (u32)ci2*4;
            *(u32*)(sm + off)         = sh[e];
            *(u32*)(sm + off + APART) = sl[e];
        }
    };

    load_row(0); load_row(1);
    __syncthreads();

    const u32 laneA = (u32)((t & 15)*144 + (t >> 4)*16);
    const u32 laneB = (u32)((t & 15)*80  + (t >> 4)*16);
    const int quad = t >> 2, qi = t & 3;
    const bool act = ((quad & 1) == 0);
    float* op = out + (size_t)img*262144 + (size_t)half*32*4096;

    float prev[4][4];
    #pragma unroll
    for (int nt=0;nt<4;nt++)
        #pragma unroll
        for (int r=0;r<4;r++) prev[nt][r] = 0.f;

    #pragma unroll 1
    for (int y = 0; y < 128; y++){
        float d[4][4];
        #pragma unroll
        for (int nt=0;nt<4;nt++)
            #pragma unroll
            for (int r=0;r<4;r++) d[nt][r] = 0.f;

        #pragma unroll
        for (int dy = 0; dy < 3; dy++){
            int iy = y + dy - 1;
            if ((unsigned)iy >= 128u) continue;
            u32 slotBase = SB + SMA + (u32)((y+dy)%3)*SLOT;
            #pragma unroll
            for (int dx = 0; dx < 3; dx++){
                int tp = (dy*3+dx)*2;
                u32 aB = slotBase + (u32)(m0+dx)*144 + laneA;
                u32 bB = SB + SMB + (u32)tp*5120 + laneB;
                #pragma unroll
                for (int ks = 0; ks < 4; ks++){
                    u32 aH[4], aL[4], bH0[4], bH1[4], bL0[4], bL1[4];
                    ldsm4 (aH,  aB + ks*32);
                    ldsm4 (aL,  aB + APART + ks*32);
                    ldsm4t(bH0, bB + ks*1280);               // n 0-15 (hi)
                    ldsm4t(bH1, bB + ks*1280 + 32);          // n 16-31 (hi)
                    ldsm4t(bL0, bB + 5120 + ks*1280);        // n 0-15 (lo)
                    ldsm4t(bL1, bB + 5120 + ks*1280 + 32);   // n 16-31 (lo)
                    // (hi,hi)
                    MMA(d[0], aH, bH0[0], bH0[1]);
                    MMA(d[1], aH, bH0[2], bH0[3]);
                    MMA(d[2], aH, bH1[0], bH1[1]);
                    MMA(d[3], aH, bH1[2], bH1[3]);
                    // (hi,lo)
                    MMA(d[0], aH, bL0[0], bL0[1]);
                    MMA(d[1], aH, bL0[2], bL0[3]);
                    MMA(d[2], aH, bL1[0], bL1[1]);
                    MMA(d[3], aH, bL1[2], bL1[3]);
                    // (lo,hi)
                    MMA(d[0], aL, bH0[0], bH0[1]);
                    MMA(d[1], aL, bH0[2], bH0[3]);
                    MMA(d[2], aL, bH1[0], bH1[1]);
                    MMA(d[3], aL, bH1[2], bH1[3]);
                }
            }
        }

        // epilogue: x-pair pool via shfl, y-pair via registers, bias+relu on odd rows
        #pragma unroll
        for (int nt = 0; nt < 4; nt++){
            #pragma unroll
            for (int r = 0; r < 4; r++){
                float v = d[nt][r];
                float p = fmaxf(v, __shfl_xor_sync(0xffffffffu, v, 4));
                if (act){
                    if ((y & 1) == 0){
                        prev[nt][r] = p;
                    } else {
                        int x2  = (m0 + quad + ((r>>1)<<3)) >> 1;
                        int ocl = nt*8 + (qi<<1) + (r&1);
                        float o = fmaxf(prev[nt][r], p) + sBias[ocl];
                        op[(size_t)ocl*4096 + ((y>>1)<<6) + x2] = fmaxf(o, 0.f);
                    }
                }
            }
        }

        __syncthreads();
        load_row(y+2);
        __syncthreads();
    }
}

// ---------------- conv1n (proven) ----------------
__global__ void __launch_bounds__(512, 2)
conv1n_kernel(const float* __restrict__ sx,
              const float* __restrict__ qx,
              const float* __restrict__ w,
              const float* __restrict__ bias,
              float* __restrict__ out)
{
    __shared__ __align__(16) float sTile[3][10][18];
    __shared__ u64 sW[64][27];

    const int tid = threadIdx.x;
    const int img = blockIdx.y;
    const int tx = blockIdx.x & 15;
    const int ty = blockIdx.x >> 4;
    const int gx0 = tx*16, gy0 = ty*8;
    const float* inImg = (img < NSUP) ? sx + (size_t)img*3*65536
                                      : qx + (size_t)(img-NSUP)*3*65536;

    for (int idx = tid; idx < 540; idx += 512){
        int k = idx/180; int rem = idx - k*180;
        int r = rem/18, c = rem - r*18;
        int iy = gy0 - 1 + r, ix = gx0 - 1 + c;
        float v = 0.f;
        if ((unsigned)iy < 256u && (unsigned)ix < 256u)
            v = inImg[k*65536 + iy*256 + ix];
        sTile[k][r][c] = v;
    }
    for (int idx = tid; idx < 1728; idx += 512){
        float v = w[idx];
        sW[idx/27][idx%27] = pk2(v, v);
    }
    __syncthreads();

    const int oc  = tid >> 3;
    const int sid = tid & 7;
    const u64* tbase = (const u64*)sTile;

    u64 acc[8];
    #pragma unroll
    for (int r = 0; r < 8; r++) acc[r] = 0ull;

    #pragma unroll
    for (int ci = 0; ci < 3; ci++){
        u64 wr[9];
        #pragma unroll
        for (int tt = 0; tt < 9; tt++) wr[tt] = sW[oc][ci*9 + tt];
        #pragma unroll
        for (int tr = 0; tr < 10; tr++){
            u64 T0 = tbase[(ci*10 + tr)*9 + sid];
            u64 T2 = tbase[(ci*10 + tr)*9 + sid + 1];
            u64 T1 = cmp2(T0, T2);
            #pragma unroll
            for (int dy = 0; dy < 3; dy++){
                const int r = tr - dy;
                if (r >= 0 && r < 8){
                    fma2(acc[r], T0, wr[dy*3+0]);
                    fma2(acc[r], T1, wr[dy*3+1]);
                    fma2(acc[r], T2, wr[dy*3+2]);
                }
            }
        }
    }

    float b = bias[oc];
    const int pxl = tx*8 + sid;
    const int py0 = ty*4;
    float* op = out + ((size_t)img*64 + oc)*16384;
    #pragma unroll
    for (int i = 0; i < 4; i++){
        float2 a0 = up2(acc[2*i]), a1 = up2(acc[2*i+1]);
        float m = fmaxf(fmaxf(a0.x, a0.y), fmaxf(a1.x, a1.y)) + b;
        op[(py0 + i)*128 + pxl] = fmaxf(m, 0.f);
    }
}

// ---------------- conv64e (proven R8): triple-buffered FFMA2 conv ----------------
template<int IN_H>
__global__ void __launch_bounds__(512,1)
conv64e_kernel(const float* __restrict__ in,
               const float* __restrict__ w,
               const float* __restrict__ bias,
               float* __restrict__ out,
               int outImgStride)
{
    constexpr int PH    = IN_H/2;
    constexpr int TILES = PH/8;
    constexpr int TI    = 18;
    constexpr int CHUNK = 8;
    constexpr int HH    = IN_H*IN_H;
    constexpr int PKN   = CHUNK*TI*17;
    constexpr int WN    = 64*CHUNK*9;

    extern __shared__ __align__(16) unsigned char smx[];
    u64* sW  = (u64*)smx;
    u64* sPk = (u64*)(smx + 3*(size_t)WN*8);

    const int tid = threadIdx.x;
    const int pos = tid & 31;
    const int ocg = tid >> 5;
    const int pr  = pos & 3;
    const int px  = pos >> 2;
    const int img = blockIdx.y;
    const int tpy = blockIdx.x / TILES, tpx = blockIdx.x % TILES;
    const int cy0 = tpy*16, cx0 = tpx*16;
    const float* inImg = in + (size_t)img*64*HH;

    int  eoff[5];
    bool ep0[5], ep1[5];
    #pragma unroll
    for (int j=0;j<5;j++){
        int e = tid + j*512;
        bool v = e < PKN;
        int ee = v ? e : 0;
        int k = ee/306, rem = ee - k*306;
        int r = rem/17,  s  = rem - r*17;
        int c0 = (s<9) ? 2*s : 2*(s-9)+1;
        int iy = cy0-1+r, ix0 = cx0-1+c0;
        bool rowok = (unsigned)iy < (unsigned)IN_H;
        ep0[j] = v && rowok && (unsigned)ix0     < (unsigned)IN_H;
        ep1[j] = v && rowok && (unsigned)(ix0+1) < (unsigned)IN_H;
        eoff[j] = k*HH + iy*IN_H + ix0;
    }
    int gwoff[9];
    #pragma unroll
    for (int j=0;j<9;j++){
        int we = tid + j*512;
        int oc = we/72, rem = we - oc*72;
        int k = rem/9,  tt  = rem - k*9;
        gwoff[j] = (oc*64 + k)*9 + tt;
    }

    u64 acc[4][4];
    #pragma unroll
    for (int o=0;o<4;o++)
        #pragma unroll
        for (int cc=0;cc<4;cc++) acc[o][cc] = 0ull;

    float f[5][2], wr[9];
    const float* pIn = inImg;
    const float* pW  = w;

    #pragma unroll
    for (int j=0;j<5;j++){
        f[j][0] = ep0[j] ? pIn[eoff[j]]   : 0.f;
        f[j][1] = ep1[j] ? pIn[eoff[j]+1] : 0.f;
    }
    #pragma unroll
    for (int j=0;j<9;j++) wr[j] = pW[gwoff[j]];
    pIn += CHUNK*HH; pW += 72;

    #pragma unroll
    for (int j=0;j<5;j++){
        int e = tid + j*512;
        if (e < PKN) *(float2*)(sPk + e) = make_float2(f[j][0], f[j][1]);
    }
    #pragma unroll
    for (int j=0;j<9;j++)
        *(float2*)(sW + tid + j*512) = make_float2(wr[j], wr[j]);

    #pragma unroll
    for (int j=0;j<5;j++){
        f[j][0] = ep0[j] ? pIn[eoff[j]]   : 0.f;
        f[j][1] = ep1[j] ? pIn[eoff[j]+1] : 0.f;
    }
    #pragma unroll
    for (int j=0;j<9;j++) wr[j] = pW[gwoff[j]];
    pIn += CHUNK*HH; pW += 72;

    __syncthreads();

    int rb = 0, wb = 1;
    #pragma unroll 1
    for (int c = 0; c < 8; c++){
        if (c < 7){
            u64* pkw = sPk + wb*PKN;
            u64* ww  = sW  + wb*WN;
            #pragma unroll
            for (int j=0;j<5;j++){
                int e = tid + j*512;
                if (e < PKN) *(float2*)(pkw + e) = make_float2(f[j][0], f[j][1]);
            }
            #pragma unroll
            for (int j=0;j<9;j++)
                *(float2*)(ww + tid + j*512) = make_float2(wr[j], wr[j]);
        }
        if (c < 6){
            #pragma unroll
            for (int j=0;j<5;j++){
                f[j][0] = ep0[j] ? pIn[eoff[j]]   : 0.f;
                f[j][1] = ep1[j] ? pIn[eoff[j]+1] : 0.f;
            }
            #pragma unroll
            for (int j=0;j<9;j++) wr[j] = pW[gwoff[j]];
            pIn += CHUNK*HH; pW += 72;
        }

        const u64* pkb = sPk + rb*PKN;
        const u64* wbb = sW  + rb*WN;
        #pragma unroll
        for (int k=0;k<CHUNK;k++){
            const u64* prow = pkb + (k*TI + 4*pr)*17;
            u64 P[6][3];
            #pragma unroll
            for (int r=0;r<6;r++){
                P[r][0] = prow[r*17 + px];
                P[r][1] = prow[r*17 + 9 + px];
                P[r][2] = prow[r*17 + px + 1];
            }
            #pragma unroll
            for (int o=0;o<4;o++){
                const u64* wp = wbb + ((ocg*4+o)*8 + k)*9;
                #pragma unroll
                for (int dy=0;dy<3;dy++){
                    u64 w0 = wp[dy*3+0], w1 = wp[dy*3+1], w2 = wp[dy*3+2];
                    #pragma unroll
                    for (int cc=0;cc<4;cc++) fma2(acc[o][cc], P[cc+dy][0], w0);
                    #pragma unroll
                    for (int cc=0;cc<4;cc++) fma2(acc[o][cc], P[cc+dy][1], w1);
                    #pragma unroll
                    for (int cc=0;cc<4;cc++) fma2(acc[o][cc], P[cc+dy][2], w2);
                }
            }
        }

        if (c == 7) break;
        __syncthreads();
        rb = wb; wb = (wb == 2) ? 0 : wb + 1;
    }

    const int gx  = tpx*8 + px;
    const int gy0 = tpy*8 + 2*pr;
    #pragma unroll
    for (int o=0;o<4;o++){
        int oc = ocg*4 + o;
        float b = bias[oc];
        float2 a0 = up2(acc[o][0]), a1 = up2(acc[o][1]);
        float2 a2 = up2(acc[o][2]), a3 = up2(acc[o][3]);
        float m0 = fmaxf(fmaxf(a0.x,a0.y), fmaxf(a1.x,a1.y)) + b; m0 = fmaxf(m0, 0.f);
        float m1 = fmaxf(fmaxf(a2.x,a2.y), fmaxf(a3.x,a3.y)) + b; m1 = fmaxf(m1, 0.f);
        float* op = out + (size_t)img*outImgStride + (size_t)oc*PH*PH;
        op[(size_t)gy0*PH + gx]     = m0;
        op[(size_t)(gy0+1)*PH + gx] = m1;
    }
}

// ---------------- conv6 (proven) ----------------
template<int IN_H, int TILE_P>
__global__ void conv64_kernel(const float* __restrict__ in,
                              const float* __restrict__ w,
                              const float* __restrict__ bias,
                              float* __restrict__ out,
                              int outImgStride)
{
    constexpr int PH    = IN_H/2;
    constexpr int TILES = PH / TILE_P;
    constexpr int TI    = TILE_P*2 + 2;
    constexpr int POS   = TILE_P*TILE_P;
    constexpr int NT    = POS*8;
    constexpr int CHUNK = 8;

    __shared__ __align__(16) float sIn[CHUNK][TI][TI];
    __shared__ u64 sW[64][CHUNK][9];

    const int tid = threadIdx.x;
    const int pos = tid & (POS-1);
    const int ocg = tid / POS;
    const int py = pos / TILE_P, px = pos % TILE_P;
    const int img = blockIdx.y;
    const int tpy = blockIdx.x / TILES, tpx = blockIdx.x % TILES;
    const int cy0 = tpy*TILE_P*2, cx0 = tpx*TILE_P*2;
    const float* inImg = in + (size_t)img*64*IN_H*IN_H;

    u64 accA[8], accB[8];
    #pragma unroll
    for (int i=0;i<8;i++){ accA[i]=0ull; accB[i]=0ull; }

    for (int ci0 = 0; ci0 < 64; ci0 += CHUNK){
        for (int idx = tid; idx < CHUNK*TI*TI; idx += NT){
            int k = idx/(TI*TI), rem = idx%(TI*TI);
            int r = rem/TI, c = rem%TI;
            int iy = cy0-1+r, ix = cx0-1+c;
            float v = 0.f;
            if (iy>=0 && iy<IN_H && ix>=0 && ix<IN_H)
                v = inImg[(size_t)(ci0+k)*IN_H*IN_H + (size_t)iy*IN_H + ix];
            sIn[k][r][c] = v;
        }
        for (int idx = tid; idx < 64*CHUNK*9; idx += NT){
            int oc = idx/(CHUNK*9), rem = idx%(CHUNK*9);
            int k = rem/9, tt = rem%9;
            float wv = w[(oc*64 + (ci0+k))*9 + tt];
            sW[oc][k][tt] = pk2(wv, wv);
        }
        __syncthreads();

        #pragma unroll
        for (int k=0;k<CHUNK;k++){
            u64 P[4][3];
            #pragma unroll
            for (int r=0;r<4;r++){
                float2 a = *(const float2*)&sIn[k][2*py+r][2*px];
                float2 b = *(const float2*)&sIn[k][2*py+r][2*px+2];
                P[r][0] = pk2(a.x, a.y);
                P[r][1] = pk2(a.y, b.x);
                P[r][2] = pk2(b.x, b.y);
            }
            #pragma unroll
            for (int o=0;o<8;o++){
                const u64* wp = &sW[ocg*8+o][k][0];
                #pragma unroll
                for (int dy=0;dy<3;dy++){
                    #pragma unroll
                    for (int dx=0;dx<3;dx++){
                        u64 wv = wp[dy*3+dx];
                        fma2(accA[o], P[dy][dx],   wv);
                        fma2(accB[o], P[dy+1][dx], wv);
                    }
                }
            }
        }
        __syncthreads();
    }

    const int gy = tpy*TILE_P+py, gx = tpx*TILE_P+px;
    #pragma unroll
    for (int o=0;o<8;o++){
        int oc = ocg*8+o;
        float2 ca = up2(accA[o]); float2 cb = up2(accB[o]);
        float m = fmaxf(fmaxf(ca.x,ca.y), fmaxf(cb.x,cb.y)) + bias[oc];
        m = fmaxf(m, 0.f);
        out[(size_t)img*outImgStride + (size_t)oc*PH*PH + (size_t)gy*PH + gx] = m;
    }
}

// ---------------- small kernels (proven) ----------------
__global__ void zero_kernel(float* __restrict__ p, int n){
    int i = blockIdx.x*256 + threadIdx.x;
    if (i < n) p[i] = 0.f;
}

__global__ void scatter_kernel(const float* __restrict__ feat, int stride, int colOff,
                               const int* __restrict__ ei, int E, int base,
                               float* __restrict__ agg, float* __restrict__ cnt)
{
    int e = blockIdx.x;
    int src = ei[e], dst = ei[E + e];
    const float* f = feat + (size_t)(base+src)*stride + colOff;
    float* a = agg + (size_t)(base+dst)*1024;
    for (int d = threadIdx.x; d < 1024; d += blockDim.x)
        atomicAdd(&a[d], f[d]);
    if (threadIdx.x == 0) atomicAdd(&cnt[base+dst], 1.f);
}

__global__ void combine_kernel(const float* __restrict__ feat, int fstride, int fcolOff,
                               const float* __restrict__ agg, const float* __restrict__ cnt,
                               float* __restrict__ outp, int ostride, int ocolOff)
{
    int i = blockIdx.x*256 + threadIdx.x;
    if (i >= NTOT*1024) return;
    int n = i >> 10, d = i & 1023;
    float c = fmaxf(cnt[n], 1.f);
    float fv = feat[(size_t)n*fstride + fcolOff + d];
    outp[(size_t)n*ostride + ocolOff + d] = (agg[i]/c) * fv;
}

__global__ void gemm_bias_kernel(const float* __restrict__ A, int lda,
                                 const float* __restrict__ W,
                                 const float* __restrict__ bias,
                                 float* __restrict__ C, int M, int K)
{
    __shared__ float sA[16][17];
    __shared__ float sB[16][64];
    int tx = threadIdx.x & 15, ty = threadIdx.x >> 4;
    int n0 = blockIdx.x*64, m0 = blockIdx.y*16;
    float acc[4] = {0.f,0.f,0.f,0.f};
    for (int k0 = 0; k0 < K; k0 += 16){
        int m = m0 + ty;
        sA[ty][tx] = (m < M) ? A[(size_t)m*lda + k0 + tx] : 0.f;
        #pragma unroll
        for (int j=0;j<4;j++)
            sB[ty][tx*4+j] = W[(size_t)(k0+ty)*1024 + n0 + tx*4 + j];
        __syncthreads();
        #pragma unroll
        for (int kk=0;kk<16;kk++){
            float a = sA[ty][kk];
            #pragma unroll
            for (int j=0;j<4;j++) acc[j] += a * sB[kk][tx*4+j];
        }
        __syncthreads();
    }
    int m = m0 + ty;
    if (m < M){
        #pragma unroll
        for (int j=0;j<4;j++)
            C[(size_t)m*1024 + n0 + tx*4 + j] = acc[j] + bias[n0 + tx*4 + j];
    }
}

__global__ void pair_kernel(const float* __restrict__ feat,
                            const float* __restrict__ center,
                            float* __restrict__ bmat)
{
    int s = blockIdx.x, q = blockIdx.y;
    const float* qf = feat + (size_t)(NSUP+q)*1024;
    const float* sf = feat + (size_t)s*1024;
    const float* cf = center + (size_t)(s/5)*1024;
    __shared__ float su[1024];
    __shared__ float rA[256], rB[256], rC[256];
    __shared__ float sS1, sS2;
    int tid = threadIdx.x;

    float S1 = 0.f, S2 = 0.f, M = -1e30f;
    for (int d = tid; d < 1024; d += 256){
        float qd = qf[d], sd = sf[d];
        float df = sd - qd;
        float u = expf(-df*df);
        su[d] = u;
        S2 += u; M = fmaxf(M, u);
        float sc = 0.25f*cf[d] + 0.5f*sd;
        float d2 = sc - qd;
        S1 += expf(-d2*d2);
    }
    rA[tid]=S1; rB[tid]=S2; rC[tid]=M;
    __syncthreads();
    for (int o=128;o>0;o>>=1){
        if (tid<o){ rA[tid]+=rA[tid+o]; rB[tid]+=rB[tid+o]; rC[tid]=fmaxf(rC[tid],rC[tid+o]); }
        __syncthreads();
    }
    if (tid==0){ sS1 = rA[0]; sS2 = rB[0]; }
    float Mv = rC[0];
    __syncthreads();

    float Se = 0.f;
    for (int d = tid; d < 1024; d += 256) Se += expf(su[d] - Mv);
    rA[tid] = Se;
    __syncthreads();
    for (int o=128;o>0;o>>=1){ if (tid<o) rA[tid]+=rA[tid+o]; __syncthreads(); }
    if (tid==0)
        bmat[q*NSUP + s] = sS1 + sS2 - 1024.f*(Mv + logf(rA[0]));
}

__global__ void dis_kernel(const float* __restrict__ bmat,
                           const int* __restrict__ sy,
                           float* __restrict__ dis)
{
    int q = blockIdx.x;
    __shared__ float row[NSUP];
    __shared__ float red[128];
    int tid = threadIdx.x;
    float m = -1e30f;
    for (int s = tid; s < NSUP; s += 128){ row[s] = bmat[q*NSUP+s]; m = fmaxf(m, row[s]); }
    red[tid] = m; __syncthreads();
    for (int o=64;o>0;o>>=1){ if (tid<o) red[tid]=fmaxf(red[tid],red[tid+o]); __syncthreads(); }
    float mv = red[0]; __syncthreads();
    float se = 0.f;
    for (int s = tid; s < NSUP; s += 128) se += expf(row[s]-mv);
    red[tid] = se; __syncthreads();
    for (int o=64;o>0;o>>=1){ if (tid<o) red[tid]+=red[tid+o]; __syncthreads(); }
    float lse = mv + logf(red[0]);
    if (tid < NCLS){
        float sum = 0.f, cntc = 0.f;
        for (int s=0;s<NSUP;s++) if (sy[s]==tid){ sum += row[s]-lse; cntc += 1.f; }
        dis[q*NCLS+tid] = sum / fmaxf(cntc, 1.f);
    }
}

__global__ void center_kernel(const float* __restrict__ feat,
                              const int* __restrict__ sy,
                              const float* __restrict__ center,
                              float* __restrict__ outp)
{
    int c = blockIdx.x;
    int d = blockIdx.y*256 + threadIdx.x;
    __shared__ int ssy[NSUP];
    for (int s = threadIdx.x; s < NSUP; s += 256) ssy[s] = sy[s];
    __syncthreads();
    float sum = 0.f, cnt = 0.f;
    for (int s=0;s<NSUP;s++) if (ssy[s]==c){ sum += feat[(size_t)s*1024 + d]; cnt += 1.f; }
    outp[c*1024 + d] = (sum/fmaxf(cnt,1.f))*0.5f + 0.25f*center[c*1024 + d];
}

__global__ void loss_kernel(const float* __restrict__ dis,
                            const int* __restrict__ qy,
                            float* __restrict__ outp)
{
    __shared__ float sl[32], sa[32];
    int q = threadIdx.x;
    float l = 0.f, a = 0.f;
    if (q < NQRY){
        const float* r = dis + q*NCLS;
        float best = -1e30f; int arg = 0; float m = -1e30f;
        for (int j=0;j<NCLS;j++){
            float v = r[j];
            if (v > best){ best = v; arg = j; }
            m = fmaxf(m, v);
        }
        float se = 0.f;
        for (int j=0;j<NCLS;j++) se += expf(r[j]-m);
        float lse = m + logf(se);
        int y = qy[q];
        l = lse - r[y];
        a = (arg == y) ? 1.f : 0.f;
    }
    sl[threadIdx.x] = l; sa[threadIdx.x] = a;
    __syncthreads();
    if (threadIdx.x == 0){
        float L=0.f, A=0.f;
        for (int i=0;i<32;i++){ L += sl[i]; A += sa[i]; }
        outp[0] = L; outp[1] = A;
    }
}

// ---------------- host launcher ----------------
extern "C" void kernel_launch(void* const* d_in, const int* in_sizes, int n_in,
                              void* d_out, int out_size)
{
    const float* support_x = (const float*)d_in[0];
    const int*   sup_ei    = (const int*)  d_in[1];
    const int*   sup_y     = (const int*)  d_in[3];
    const float* query_x   = (const float*)d_in[4];
    const int*   qry_ei    = (const int*)  d_in[5];
    const int*   qry_y     = (const int*)  d_in[7];
    const float* center    = (const float*)d_in[8];
    const float* cw1       = (const float*)d_in[9];
    const float* cb1       = (const float*)d_in[10];
    const float* cw_rest   = (const float*)d_in[11];
    const float* cb_rest   = (const float*)d_in[12];
    const float* lin2_w    = (const float*)d_in[13];
    const float* lin2_b    = (const float*)d_in[14];
    const float* mlp_w     = (const float*)d_in[15];
    const float* mlp_b     = (const float*)d_in[16];
    float* out = (float*)d_out;

    int Es = in_sizes[1] / 2;
    int Eq = in_sizes[5] / 2;

    float *buf0, *buf1, *cat, *tmp, *h2, *feat, *agg, *cnt, *bmat, *dis;
    __nv_bfloat16 *ahi, *alo, *wbp;
    cudaGetSymbolAddress((void**)&buf0, g_buf0);
    cudaGetSymbolAddress((void**)&buf1, g_buf1);
    cudaGetSymbolAddress((void**)&ahi,  g_ahi);
    cudaGetSymbolAddress((void**)&alo,  g_alo);
    cudaGetSymbolAddress((void**)&wbp,  g_wb);
    cudaGetSymbolAddress((void**)&cat,  g_cat);
    cudaGetSymbolAddress((void**)&tmp,  g_tmp);
    cudaGetSymbolAddress((void**)&h2,   g_h2);
    cudaGetSymbolAddress((void**)&feat, g_feat);
    cudaGetSymbolAddress((void**)&agg,  g_agg);
    cudaGetSymbolAddress((void**)&cnt,  g_cnt);
    cudaGetSymbolAddress((void**)&bmat, g_b);
    cudaGetSymbolAddress((void**)&dis,  g_dis);

    const size_t SMEMB = 3*4608*8 + 3*2448*8;           // conv64e: 169344
    const size_t SMEMT = 92160 + 2*56160 + 128;         // tconv2m: 204608
    static int attr_done = 0;
    if (!attr_done){
        cudaFuncSetAttribute(tconv2m_kernel,     cudaFuncAttributeMaxDynamicSharedMemorySize, (int)SMEMT);
        cudaFuncSetAttribute(conv64e_kernel<64>, cudaFuncAttributeMaxDynamicSharedMemorySize, (int)SMEMB);
        cudaFuncSetAttribute(conv64e_kernel<32>, cudaFuncAttributeMaxDynamicSharedMemorySize, (int)SMEMB);
        cudaFuncSetAttribute(conv64e_kernel<16>, cudaFuncAttributeMaxDynamicSharedMemorySize, (int)SMEMB);
        attr_done = 1;
    }

    const int NG = (NTOT*1024 + 255)/256;
    const int WSTR = 64*64*9;

    // capture slot = launch #4 -> tconv2m
    wb2_kernel<<<(73728 + 255)/256, 256>>>(cw_rest, wbp);                           // #1
    conv1n_kernel<<<dim3(512, NTOT), 512>>>(support_x, query_x, cw1, cb1, buf0);    // #2
    tr_kernel<<<dim3(128, NTOT), 256>>>(buf0, ahi, alo);                            // #3
    tconv2m_kernel<<<dim3(2, NTOT), 256, SMEMT>>>(ahi, alo, wbp, cb_rest, buf1);    // #4 captured
    conv64e_kernel<64><<<dim3(16, NTOT), 512, SMEMB>>>(buf1, cw_rest+1*WSTR, cb_rest+64,  buf0, 64*32*32);
    conv64e_kernel<32><<<dim3( 4, NTOT), 512, SMEMB>>>(buf0, cw_rest+2*WSTR, cb_rest+128, buf1, 64*16*16);
    conv64e_kernel<16><<<dim3( 1, NTOT), 512, SMEMB>>>(buf1, cw_rest+3*WSTR, cb_rest+192, buf0, 64*8*8);
    conv64_kernel<8,4><<<dim3( 1, NTOT), 128>>>(buf0, cw_rest+4*WSTR, cb_rest+256, cat, 2048);

    zero_kernel<<<NG,256>>>(agg, NTOT*1024);
    zero_kernel<<<1,256>>>(cnt, NTOT);

    // ---- graph conv 1 ----
    scatter_kernel<<<Es,256>>>(cat, 2048, 0, sup_ei, Es, 0,    agg, cnt);
    scatter_kernel<<<Eq,256>>>(cat, 2048, 0, qry_ei, Eq, NSUP, agg, cnt);
    combine_kernel<<<NG,256>>>(cat, 2048, 0, agg, cnt, tmp, 1024, 0);

    gemm_bias_kernel<<<dim3(16,(NTOT+15)/16),256>>>(tmp, 1024, lin2_w, lin2_b, h2, NTOT, 1024);

    // ---- graph conv 2 ----
    zero_kernel<<<NG,256>>>(agg, NTOT*1024);
    zero_kernel<<<1,256>>>(cnt, NTOT);
    scatter_kernel<<<Es,256>>>(h2, 1024, 0, sup_ei, Es, 0,    agg, cnt);
    scatter_kernel<<<Eq,256>>>(h2, 1024, 0, qry_ei, Eq, NSUP, agg, cnt);
    combine_kernel<<<NG,256>>>(h2, 1024, 0, agg, cnt, cat, 2048, 1024);

    gemm_bias_kernel<<<dim3(16,(NTOT+15)/16),256>>>(cat, 2048, mlp_w, mlp_b, feat, NTOT, 2048);

    pair_kernel<<<dim3(NSUP, NQRY), 256>>>(feat, center, bmat);
    dis_kernel<<<NQRY,128>>>(bmat, sup_y, dis);

    center_kernel<<<dim3(NCLS,4),256>>>(feat, sup_y, center, out + 2);
    loss_kernel<<<1,32>>>(dis, qry_y, out);
}

// round 14
// speedup vs baseline: 1.7521x; 1.2747x over previous
#include <cuda_runtime.h>
#include <cuda_bf16.h>
#include <math.h>

typedef unsigned long long u64;
typedef unsigned int u32;

// ---------------- problem constants ----------------
static const int NSUP  = 115;
static const int NQRY  = 23;
static const int NTOT  = 138;
static const int NCLS  = 23;

// ---------------- device scratch ----------------
__device__ float g_buf0[(size_t)NTOT*64*128*128];
__device__ float g_buf1[(size_t)NTOT*64*64*64];
__device__ __nv_bfloat16 g_ahi [(size_t)NTOT*128*130*64];  // conv2 input transposed, hi
__device__ __nv_bfloat16 g_alo [(size_t)NTOT*128*130*64];  // lo
__device__ __nv_bfloat16 g_ahi2[(size_t)NTOT*64*66*64];    // conv3 input transposed, hi (borders stay 0)
__device__ __nv_bfloat16 g_alo2[(size_t)NTOT*64*66*64];    // lo
__device__ __nv_bfloat16 g_wb  [2*18*64*64];               // conv2+conv3 weights [L][tp][ci(k)][oc]
__device__ float g_cat [(size_t)NTOT*2048];
__device__ float g_tmp [(size_t)NTOT*1024];
__device__ float g_h2  [(size_t)NTOT*1024];
__device__ float g_feat[(size_t)NTOT*1024];
__device__ float g_agg [(size_t)NTOT*1024];
__device__ float g_cnt [NTOT];
__device__ float g_b   [NQRY*NSUP];
__device__ float g_dis [NQRY*NCLS];

// ---------------- packed f32x2 helpers ----------------
__device__ __forceinline__ u64 pk2(float x, float y){
    u64 r; asm("mov.b64 %0, {%1, %2};" : "=l"(r) : "f"(x), "f"(y)); return r;
}
__device__ __forceinline__ void fma2(u64 &d, u64 a, u64 b){
    asm("fma.rn.f32x2 %0, %1, %2, %0;" : "+l"(d) : "l"(a), "l"(b));
}
__device__ __forceinline__ float2 up2(u64 a){
    float2 r; asm("mov.b64 {%0, %1}, %2;" : "=f"(r.x), "=f"(r.y) : "l"(a)); return r;
}
__device__ __forceinline__ u64 cmp2(u64 a, u64 b){ return (a >> 32) | (b << 32); }

// ---------------- warp-mma helpers ----------------
__device__ __forceinline__ void ldsm4(u32* r, u32 addr){
    asm volatile("ldmatrix.sync.aligned.m8n8.x4.shared.b16 {%0,%1,%2,%3}, [%4];"
        : "=r"(r[0]),"=r"(r[1]),"=r"(r[2]),"=r"(r[3]) : "r"(addr));
}
__device__ __forceinline__ void ldsm4t(u32* r, u32 addr){
    asm volatile("ldmatrix.sync.aligned.m8n8.x4.trans.shared.b16 {%0,%1,%2,%3}, [%4];"
        : "=r"(r[0]),"=r"(r[1]),"=r"(r[2]),"=r"(r[3]) : "r"(addr));
}
#define MMA(dd, a, b0, b1) \
    asm volatile("mma.sync.aligned.m16n8k16.row.col.f32.bf16.bf16.f32 " \
        "{%0,%1,%2,%3},{%4,%5,%6,%7},{%8,%9},{%0,%1,%2,%3};" \
        : "+f"((dd)[0]),"+f"((dd)[1]),"+f"((dd)[2]),"+f"((dd)[3]) \
        : "r"((a)[0]),"r"((a)[1]),"r"((a)[2]),"r"((a)[3]), "r"(b0),"r"(b1))

// ---------------- prep: weight split for conv2+conv3, layout [L][tp][ci(k)][oc] ----------------
__global__ void wb2_kernel(const float* __restrict__ cwr, __nv_bfloat16* __restrict__ wbp)
{
    int i = blockIdx.x*256 + threadIdx.x;          // over 2*18*64*64
    if (i >= 2*73728) return;
    int L = i / 73728;
    int r = i % 73728;
    int oc = r & 63, ci = (r>>6)&63, tp = r>>12;
    int tap = tp >> 1, part = tp & 1;
    float v = cwr[(size_t)L*36864 + (oc*64 + ci)*9 + tap];
    __nv_bfloat16 h = __float2bfloat16(v);
    wbp[i] = (part == 0) ? h : __float2bfloat16(v - __bfloat162float(h));
}

// ---------------- prep: transpose conv1 out to [img][y][x+1][ci] bf16 hi/lo ----------------
__global__ void tr_kernel(const float* __restrict__ in,
                          __nv_bfloat16* __restrict__ ahi,
                          __nv_bfloat16* __restrict__ alo)
{
    __shared__ float sT[64][133];
    int y = blockIdx.x, img = blockIdx.y;
    const float* src = in + (size_t)img*64*16384 + y*128;
    for (int e = threadIdx.x; e < 64*130; e += 256){
        int ci = e / 130, xi = e - ci*130;
        int xs = xi - 1;
        float v = ((unsigned)xs < 128u) ? src[(size_t)ci*16384 + xs] : 0.f;
        sT[ci][xi] = v;
    }
    __syncthreads();
    size_t ob = (size_t)(img*128 + y)*130*64;
    for (int e = threadIdx.x; e < 130*64; e += 256){
        int xi = e >> 6, ci = e & 63;
        float v = sT[ci][xi];
        __nv_bfloat16 h = __float2bfloat16(v);
        ahi[ob + e] = h;
        alo[ob + e] = __float2bfloat16(v - __bfloat162float(h));
    }
}

// ---------------- tconv: conv3x3+bias+relu+pool2 via warp mma.sync, split-bf16 ----------------
// grid (2 halves, NTOT). WARPS = IN_H/16 (16 x each). Row loads pipelined via registers.
// OUT_TR: write transposed bf16 hi/lo [img][y2][x2+1][64] (for next tconv); else NCHW float.
template<int IN_H, bool OUT_TR>
__global__ void __launch_bounds__(2*IN_H, 1)
tconv_kernel(const __nv_bfloat16* __restrict__ ahi,
             const __nv_bfloat16* __restrict__ alo,
             const __nv_bfloat16* __restrict__ wbp,
             const float* __restrict__ bias,
             float* __restrict__ outF,
             __nv_bfloat16* __restrict__ outHi,
             __nv_bfloat16* __restrict__ outLo)
{
    constexpr int XN      = IN_H + 2;
    constexpr int WARPS   = IN_H/16;
    constexpr int THREADS = 32*WARPS;
    constexpr int PH      = IN_H/2;
    constexpr int ROWU32  = XN*32;                         // u32 per row per part
    constexpr int NSTG    = (ROWU32 + THREADS-1)/THREADS;  // 17 for both sizes
    constexpr u32 SLOT    = (u32)XN*144;
    constexpr u32 APART   = 3*SLOT;

    extern __shared__ __align__(16) unsigned char sm[];
    const u32 SB = (u32)__cvta_generic_to_shared(sm);
    const u32 SMB = 0;
    const u32 SMA = 92160;              // B: 18*5120
    float* sBias = (float*)(sm + SMA + 2*APART);

    const int tid  = threadIdx.x;
    const int warp = tid >> 5;
    const int t    = tid & 31;
    const int half = blockIdx.x;
    const int img  = blockIdx.y;
    const int m0   = warp*16;

    // ---- load B: per tp tile [64 k][32 oc], row stride 80B ----
    const u32* wb32 = (const u32*)wbp;
    for (int e = tid; e < 18432; e += THREADS){
        int oc2 = e & 15, ci = (e>>4)&63, tp = e>>10;
        u32 v = wb32[(tp*64 + ci)*32 + half*16 + oc2];
        *(u32*)(sm + SMB + (u32)tp*5120 + (u32)ci*80 + (u32)oc2*4) = v;
    }
    if (tid < 32) sBias[t] = bias[half*32 + t];

    const u32* srcH = (const u32*)(ahi + (size_t)img*IN_H*XN*64);
    const u32* srcL = (const u32*)(alo + (size_t)img*IN_H*XN*64);

    u32 fH[NSTG], fL[NSTG];
    auto stage = [&](int j){
        #pragma unroll
        for (int i = 0; i < NSTG; i++){
            int e = tid + i*THREADS;
            if (e < ROWU32){
                fH[i] = srcH[(size_t)j*ROWU32 + e];
                fL[i] = srcL[(size_t)j*ROWU32 + e];
            }
        }
    };
    auto sts = [&](int j){
        u32 slotB = SMA + (u32)((j+1)%3)*SLOT;
        #pragma unroll
        for (int i = 0; i < NSTG; i++){
            int e = tid + i*THREADS;
            if (e < ROWU32){
                int xi = e >> 5, ci2 = e & 31;
                u32 off = slotB + (u32)xi*144 + (u32)ci2*4;
                *(u32*)(sm + off)         = fH[i];
                *(u32*)(sm + off + APART) = fL[i];
            }
        }
    };

    stage(0); sts(0);
    stage(1); sts(1);
    stage(2);
    __syncthreads();

    const u32 laneA = (u32)((t & 15)*144 + (t >> 4)*16);
    const u32 laneB = (u32)((t & 15)*80  + (t >> 4)*16);
    const int quad = t >> 2, qi = t & 3;
    const bool act = ((quad & 1) == 0);
    float* opF = OUT_TR ? nullptr
               : outF + (size_t)img*64*PH*PH + (size_t)half*32*PH*PH;

    float prev[4][4];
    #pragma unroll
    for (int nt=0;nt<4;nt++)
        #pragma unroll
        for (int r=0;r<4;r++) prev[nt][r] = 0.f;

    #pragma unroll 1
    for (int y = 0; y < IN_H; y++){
        float d[4][4];
        #pragma unroll
        for (int nt=0;nt<4;nt++)
            #pragma unroll
            for (int r=0;r<4;r++) d[nt][r] = 0.f;

        #pragma unroll
        for (int dy = 0; dy < 3; dy++){
            int iy = y + dy - 1;
            if ((unsigned)iy >= (unsigned)IN_H) continue;
            u32 slotBase = SB + SMA + (u32)((y+dy)%3)*SLOT;
            #pragma unroll
            for (int dx = 0; dx < 3; dx++){
                int tp = (dy*3+dx)*2;
                u32 aB = slotBase + (u32)(m0+dx)*144 + laneA;
                u32 bB = SB + SMB + (u32)tp*5120 + laneB;
                #pragma unroll
                for (int ks = 0; ks < 4; ks++){
                    u32 aH[4], aL[4], bH0[4], bH1[4], bL0[4], bL1[4];
                    ldsm4 (aH,  aB + ks*32);
                    ldsm4 (aL,  aB + APART + ks*32);
                    ldsm4t(bH0, bB + ks*1280);
                    ldsm4t(bH1, bB + ks*1280 + 32);
                    ldsm4t(bL0, bB + 5120 + ks*1280);
                    ldsm4t(bL1, bB + 5120 + ks*1280 + 32);
                    MMA(d[0], aH, bH0[0], bH0[1]);
                    MMA(d[1], aH, bH0[2], bH0[3]);
                    MMA(d[2], aH, bH1[0], bH1[1]);
                    MMA(d[3], aH, bH1[2], bH1[3]);
                    MMA(d[0], aH, bL0[0], bL0[1]);
                    MMA(d[1], aH, bL0[2], bL0[3]);
                    MMA(d[2], aH, bL1[0], bL1[1]);
                    MMA(d[3], aH, bL1[2], bL1[3]);
                    MMA(d[0], aL, bH0[0], bH0[1]);
                    MMA(d[1], aL, bH0[2], bH0[3]);
                    MMA(d[2], aL, bH1[0], bH1[1]);
                    MMA(d[3], aL, bH1[2], bH1[3]);
                }
            }
        }

        // epilogue
        #pragma unroll
        for (int nt = 0; nt < 4; nt++){
            #pragma unroll
            for (int r = 0; r < 4; r++){
                float v = d[nt][r];
                float p = fmaxf(v, __shfl_xor_sync(0xffffffffu, v, 4));
                if (act){
                    if ((y & 1) == 0){
                        prev[nt][r] = p;
                    } else {
                        int x2  = (m0 + quad + ((r>>1)<<3)) >> 1;
                        int ocl = nt*8 + (qi<<1) + (r&1);
                        float o = fmaxf(prev[nt][r], p) + sBias[ocl];
                        o = fmaxf(o, 0.f);
                        if (OUT_TR){
                            size_t idx = (((size_t)img*PH + (y>>1))*(PH+2) + x2+1)*64 + half*32 + ocl;
                            __nv_bfloat16 h = __float2bfloat16(o);
                            outHi[idx] = h;
                            outLo[idx] = __float2bfloat16(o - __bfloat162float(h));
                        } else {
                            opF[(size_t)ocl*PH*PH + ((size_t)(y>>1))*PH + x2] = o;
                        }
                    }
                }
            }
        }

        __syncthreads();
        if (y + 2 < IN_H) sts(y+2);
        if (y + 3 < IN_H) stage(y+3);
        __syncthreads();
    }
}

// ---------------- conv1n (proven) ----------------
__global__ void __launch_bounds__(512, 2)
conv1n_kernel(const float* __restrict__ sx,
              const float* __restrict__ qx,
              const float* __restrict__ w,
              const float* __restrict__ bias,
              float* __restrict__ out)
{
    __shared__ __align__(16) float sTile[3][10][18];
    __shared__ u64 sW[64][27];

    const int tid = threadIdx.x;
    const int img = blockIdx.y;
    const int tx = blockIdx.x & 15;
    const int ty = blockIdx.x >> 4;
    const int gx0 = tx*16, gy0 = ty*8;
    const float* inImg = (img < NSUP) ? sx + (size_t)img*3*65536
                                      : qx + (size_t)(img-NSUP)*3*65536;

    for (int idx = tid; idx < 540; idx += 512){
        int k = idx/180; int rem = idx - k*180;
        int r = rem/18, c = rem - r*18;
        int iy = gy0 - 1 + r, ix = gx0 - 1 + c;
        float v = 0.f;
        if ((unsigned)iy < 256u && (unsigned)ix < 256u)
            v = inImg[k*65536 + iy*256 + ix];
        sTile[k][r][c] = v;
    }
    for (int idx = tid; idx < 1728; idx += 512){
        float v = w[idx];
        sW[idx/27][idx%27] = pk2(v, v);
    }
    __syncthreads();

    const int oc  = tid >> 3;
    const int sid = tid & 7;
    const u64* tbase = (const u64*)sTile;

    u64 acc[8];
    #pragma unroll
    for (int r = 0; r < 8; r++) acc[r] = 0ull;

    #pragma unroll
    for (int ci = 0; ci < 3; ci++){
        u64 wr[9];
        #pragma unroll
        for (int tt = 0; tt < 9; tt++) wr[tt] = sW[oc][ci*9 + tt];
        #pragma unroll
        for (int tr = 0; tr < 10; tr++){
            u64 T0 = tbase[(ci*10 + tr)*9 + sid];
            u64 T2 = tbase[(ci*10 + tr)*9 + sid + 1];
            u64 T1 = cmp2(T0, T2);
            #pragma unroll
            for (int dy = 0; dy < 3; dy++){
                const int r = tr - dy;
                if (r >= 0 && r < 8){
                    fma2(acc[r], T0, wr[dy*3+0]);
                    fma2(acc[r], T1, wr[dy*3+1]);
                    fma2(acc[r], T2, wr[dy*3+2]);
                }
            }
        }
    }

    float b = bias[oc];
    const int pxl = tx*8 + sid;
    const int py0 = ty*4;
    float* op = out + ((size_t)img*64 + oc)*16384;
    #pragma unroll
    for (int i = 0; i < 4; i++){
        float2 a0 = up2(acc[2*i]), a1 = up2(acc[2*i+1]);
        float m = fmaxf(fmaxf(a0.x, a0.y), fmaxf(a1.x, a1.y)) + b;
        op[(py0 + i)*128 + pxl] = fmaxf(m, 0.f);
    }
}

// ---------------- conv64e (proven): triple-buffered FFMA2 conv ----------------
template<int IN_H>
__global__ void __launch_bounds__(512,1)
conv64e_kernel(const float* __restrict__ in,
               const float* __restrict__ w,
               const float* __restrict__ bias,
               float* __restrict__ out,
               int outImgStride)
{
    constexpr int PH    = IN_H/2;
    constexpr int TILES = PH/8;
    constexpr int TI    = 18;
    constexpr int CHUNK = 8;
    constexpr int HH    = IN_H*IN_H;
    constexpr int PKN   = CHUNK*TI*17;
    constexpr int WN    = 64*CHUNK*9;

    extern __shared__ __align__(16) unsigned char smx[];
    u64* sW  = (u64*)smx;
    u64* sPk = (u64*)(smx + 3*(size_t)WN*8);

    const int tid = threadIdx.x;
    const int pos = tid & 31;
    const int ocg = tid >> 5;
    const int pr  = pos & 3;
    const int px  = pos >> 2;
    const int img = blockIdx.y;
    const int tpy = blockIdx.x / TILES, tpx = blockIdx.x % TILES;
    const int cy0 = tpy*16, cx0 = tpx*16;
    const float* inImg = in + (size_t)img*64*HH;

    int  eoff[5];
    bool ep0[5], ep1[5];
    #pragma unroll
    for (int j=0;j<5;j++){
        int e = tid + j*512;
        bool v = e < PKN;
        int ee = v ? e : 0;
        int k = ee/306, rem = ee - k*306;
        int r = rem/17,  s  = rem - r*17;
        int c0 = (s<9) ? 2*s : 2*(s-9)+1;
        int iy = cy0-1+r, ix0 = cx0-1+c0;
        bool rowok = (unsigned)iy < (unsigned)IN_H;
        ep0[j] = v && rowok && (unsigned)ix0     < (unsigned)IN_H;
        ep1[j] = v && rowok && (unsigned)(ix0+1) < (unsigned)IN_H;
        eoff[j] = k*HH + iy*IN_H + ix0;
    }
    int gwoff[9];
    #pragma unroll
    for (int j=0;j<9;j++){
        int we = tid + j*512;
        int oc = we/72, rem = we - oc*72;
        int k = rem/9,  tt  = rem - k*9;
        gwoff[j] = (oc*64 + k)*9 + tt;
    }

    u64 acc[4][4];
    #pragma unroll
    for (int o=0;o<4;o++)
        #pragma unroll
        for (int cc=0;cc<4;cc++) acc[o][cc] = 0ull;

    float f[5][2], wr[9];
    const float* pIn = inImg;
    const float* pW  = w;

    #pragma unroll
    for (int j=0;j<5;j++){
        f[j][0] = ep0[j] ? pIn[eoff[j]]   : 0.f;
        f[j][1] = ep1[j] ? pIn[eoff[j]+1] : 0.f;
    }
    #pragma unroll
    for (int j=0;j<9;j++) wr[j] = pW[gwoff[j]];
    pIn += CHUNK*HH; pW += 72;

    #pragma unroll
    for (int j=0;j<5;j++){
        int e = tid + j*512;
        if (e < PKN) *(float2*)(sPk + e) = make_float2(f[j][0], f[j][1]);
    }
    #pragma unroll
    for (int j=0;j<9;j++)
        *(float2*)(sW + tid + j*512) = make_float2(wr[j], wr[j]);

    #pragma unroll
    for (int j=0;j<5;j++){
        f[j][0] = ep0[j] ? pIn[eoff[j]]   : 0.f;
        f[j][1] = ep1[j] ? pIn[eoff[j]+1] : 0.f;
    }
    #pragma unroll
    for (int j=0;j<9;j++) wr[j] = pW[gwoff[j]];
    pIn += CHUNK*HH; pW += 72;

    __syncthreads();

    int rb = 0, wb = 1;
    #pragma unroll 1
    for (int c = 0; c < 8; c++){
        if (c < 7){
            u64* pkw = sPk + wb*PKN;
            u64* ww  = sW  + wb*WN;
            #pragma unroll
            for (int j=0;j<5;j++){
                int e = tid + j*512;
                if (e < PKN) *(float2*)(pkw + e) = make_float2(f[j][0], f[j][1]);
            }
            #pragma unroll
            for (int j=0;j<9;j++)
                *(float2*)(ww + tid + j*512) = make_float2(wr[j], wr[j]);
        }
        if (c < 6){
            #pragma unroll
            for (int j=0;j<5;j++){
                f[j][0] = ep0[j] ? pIn[eoff[j]]   : 0.f;
                f[j][1] = ep1[j] ? pIn[eoff[j]+1] : 0.f;
            }
            #pragma unroll
            for (int j=0;j<9;j++) wr[j] = pW[gwoff[j]];
            pIn += CHUNK*HH; pW += 72;
        }

        const u64* pkb = sPk + rb*PKN;
        const u64* wbb = sW  + rb*WN;
        #pragma unroll
        for (int k=0;k<CHUNK;k++){
            const u64* prow = pkb + (k*TI + 4*pr)*17;
            u64 P[6][3];
            #pragma unroll
            for (int r=0;r<6;r++){
                P[r][0] = prow[r*17 + px];
                P[r][1] = prow[r*17 + 9 + px];
                P[r][2] = prow[r*17 + px + 1];
            }
            #pragma unroll
            for (int o=0;o<4;o++){
                const u64* wp = wbb + ((ocg*4+o)*8 + k)*9;
                #pragma unroll
                for (int dy=0;dy<3;dy++){
                    u64 w0 = wp[dy*3+0], w1 = wp[dy*3+1], w2 = wp[dy*3+2];
                    #pragma unroll
                    for (int cc=0;cc<4;cc++) fma2(acc[o][cc], P[cc+dy][0], w0);
                    #pragma unroll
                    for (int cc=0;cc<4;cc++) fma2(acc[o][cc], P[cc+dy][1], w1);
                    #pragma unroll
                    for (int cc=0;cc<4;cc++) fma2(acc[o][cc], P[cc+dy][2], w2);
                }
            }
        }

        if (c == 7) break;
        __syncthreads();
        rb = wb; wb = (wb == 2) ? 0 : wb + 1;
    }

    const int gx  = tpx*8 + px;
    const int gy0 = tpy*8 + 2*pr;
    #pragma unroll
    for (int o=0;o<4;o++){
        int oc = ocg*4 + o;
        float b = bias[oc];
        float2 a0 = up2(acc[o][0]), a1 = up2(acc[o][1]);
        float2 a2 = up2(acc[o][2]), a3 = up2(acc[o][3]);
        float m0 = fmaxf(fmaxf(a0.x,a0.y), fmaxf(a1.x,a1.y)) + b; m0 = fmaxf(m0, 0.f);
        float m1 = fmaxf(fmaxf(a2.x,a2.y), fmaxf(a3.x,a3.y)) + b; m1 = fmaxf(m1, 0.f);
        float* op = out + (size_t)img*outImgStride + (size_t)oc*PH*PH;
        op[(size_t)gy0*PH + gx]     = m0;
        op[(size_t)(gy0+1)*PH + gx] = m1;
    }
}

// ---------------- conv6 (proven) ----------------
template<int IN_H, int TILE_P>
__global__ void conv64_kernel(const float* __restrict__ in,
                              const float* __restrict__ w,
                              const float* __restrict__ bias,
                              float* __restrict__ out,
                              int outImgStride)
{
    constexpr int PH    = IN_H/2;
    constexpr int TILES = PH / TILE_P;
    constexpr int TI    = TILE_P*2 + 2;
    constexpr int POS   = TILE_P*TILE_P;
    constexpr int NT    = POS*8;
    constexpr int CHUNK = 8;

    __shared__ __align__(16) float sIn[CHUNK][TI][TI];
    __shared__ u64 sW[64][CHUNK][9];

    const int tid = threadIdx.x;
    const int pos = tid & (POS-1);
    const int ocg = tid / POS;
    const int py = pos / TILE_P, px = pos % TILE_P;
    const int img = blockIdx.y;
    const int tpy = blockIdx.x / TILES, tpx = blockIdx.x % TILES;
    const int cy0 = tpy*TILE_P*2, cx0 = tpx*TILE_P*2;
    const float* inImg = in + (size_t)img*64*IN_H*IN_H;

    u64 accA[8], accB[8];
    #pragma unroll
    for (int i=0;i<8;i++){ accA[i]=0ull; accB[i]=0ull; }

    for (int ci0 = 0; ci0 < 64; ci0 += CHUNK){
        for (int idx = tid; idx < CHUNK*TI*TI; idx += NT){
            int k = idx/(TI*TI), rem = idx%(TI*TI);
            int r = rem/TI, c = rem%TI;
            int iy = cy0-1+r, ix = cx0-1+c;
            float v = 0.f;
            if (iy>=0 && iy<IN_H && ix>=0 && ix<IN_H)
                v = inImg[(size_t)(ci0+k)*IN_H*IN_H + (size_t)iy*IN_H + ix];
            sIn[k][r][c] = v;
        }
        for (int idx = tid; idx < 64*CHUNK*9; idx += NT){
            int oc = idx/(CHUNK*9), rem = idx%(CHUNK*9);
            int k = rem/9, tt = rem%9;
            float wv = w[(oc*64 + (ci0+k))*9 + tt];
            sW[oc][k][tt] = pk2(wv, wv);
        }
        __syncthreads();

        #pragma unroll
        for (int k=0;k<CHUNK;k++){
            u64 P[4][3];
            #pragma unroll
            for (int r=0;r<4;r++){
                float2 a = *(const float2*)&sIn[k][2*py+r][2*px];
                float2 b = *(const float2*)&sIn[k][2*py+r][2*px+2];
                P[r][0] = pk2(a.x, a.y);
                P[r][1] = pk2(a.y, b.x);
                P[r][2] = pk2(b.x, b.y);
            }
            #pragma unroll
            for (int o=0;o<8;o++){
                const u64* wp = &sW[ocg*8+o][k][0];
                #pragma unroll
                for (int dy=0;dy<3;dy++){
                    #pragma unroll
                    for (int dx=0;dx<3;dx++){
                        u64 wv = wp[dy*3+dx];
                        fma2(accA[o], P[dy][dx],   wv);
                        fma2(accB[o], P[dy+1][dx], wv);
                    }
                }
            }
        }
        __syncthreads();
    }

    const int gy = tpy*TILE_P+py, gx = tpx*TILE_P+px;
    #pragma unroll
    for (int o=0;o<8;o++){
        int oc = ocg*8+o;
        float2 ca = up2(accA[o]); float2 cb = up2(accB[o]);
        float m = fmaxf(fmaxf(ca.x,ca.y), fmaxf(cb.x,cb.y)) + bias[oc];
        m = fmaxf(m, 0.f);
        out[(size_t)img*outImgStride + (size_t)oc*PH*PH + (size_t)gy*PH + gx] = m;
    }
}

// ---------------- small kernels (proven) ----------------
__global__ void zero_kernel(float* __restrict__ p, int n){
    int i = blockIdx.x*256 + threadIdx.x;
    if (i < n) p[i] = 0.f;
}

__global__ void scatter_kernel(const float* __restrict__ feat, int stride, int colOff,
                               const int* __restrict__ ei, int E, int base,
                               float* __restrict__ agg, float* __restrict__ cnt)
{
    int e = blockIdx.x;
    int src = ei[e], dst = ei[E + e];
    const float* f = feat + (size_t)(base+src)*stride + colOff;
    float* a = agg + (size_t)(base+dst)*1024;
    for (int d = threadIdx.x; d < 1024; d += blockDim.x)
        atomicAdd(&a[d], f[d]);
    if (threadIdx.x == 0) atomicAdd(&cnt[base+dst], 1.f);
}

__global__ void combine_kernel(const float* __restrict__ feat, int fstride, int fcolOff,
                               const float* __restrict__ agg, const float* __restrict__ cnt,
                               float* __restrict__ outp, int ostride, int ocolOff)
{
    int i = blockIdx.x*256 + threadIdx.x;
    if (i >= NTOT*1024) return;
    int n = i >> 10, d = i & 1023;
    float c = fmaxf(cnt[n], 1.f);
    float fv = feat[(size_t)n*fstride + fcolOff + d];
    outp[(size_t)n*ostride + ocolOff + d] = (agg[i]/c) * fv;
}

__global__ void gemm_bias_kernel(const float* __restrict__ A, int lda,
                                 const float* __restrict__ W,
                                 const float* __restrict__ bias,
                                 float* __restrict__ C, int M, int K)
{
    __shared__ float sA[16][17];
    __shared__ float sB[16][64];
    int tx = threadIdx.x & 15, ty = threadIdx.x >> 4;
    int n0 = blockIdx.x*64, m0 = blockIdx.y*16;
    float acc[4] = {0.f,0.f,0.f,0.f};
    for (int k0 = 0; k0 < K; k0 += 16){
        int m = m0 + ty;
        sA[ty][tx] = (m < M) ? A[(size_t)m*lda + k0 + tx] : 0.f;
        #pragma unroll
        for (int j=0;j<4;j++)
            sB[ty][tx*4+j] = W[(size_t)(k0+ty)*1024 + n0 + tx*4 + j];
        __syncthreads();
        #pragma unroll
        for (int kk=0;kk<16;kk++){
            float a = sA[ty][kk];
            #pragma unroll
            for (int j=0;j<4;j++) acc[j] += a * sB[kk][tx*4+j];
        }
        __syncthreads();
    }
    int m = m0 + ty;
    if (m < M){
        #pragma unroll
        for (int j=0;j<4;j++)
            C[(size_t)m*1024 + n0 + tx*4 + j] = acc[j] + bias[n0 + tx*4 + j];
    }
}

__global__ void pair_kernel(const float* __restrict__ feat,
                            const float* __restrict__ center,
                            float* __restrict__ bmat)
{
    int s = blockIdx.x, q = blockIdx.y;
    const float* qf = feat + (size_t)(NSUP+q)*1024;
    const float* sf = feat + (size_t)s*1024;
    const float* cf = center + (size_t)(s/5)*1024;
    __shared__ float su[1024];
    __shared__ float rA[256], rB[256], rC[256];
    __shared__ float sS1, sS2;
    int tid = threadIdx.x;

    float S1 = 0.f, S2 = 0.f, M = -1e30f;
    for (int d = tid; d < 1024; d += 256){
        float qd = qf[d], sd = sf[d];
        float df = sd - qd;
        float u = expf(-df*df);
        su[d] = u;
        S2 += u; M = fmaxf(M, u);
        float sc = 0.25f*cf[d] + 0.5f*sd;
        float d2 = sc - qd;
        S1 += expf(-d2*d2);
    }
    rA[tid]=S1; rB[tid]=S2; rC[tid]=M;
    __syncthreads();
    for (int o=128;o>0;o>>=1){
        if (tid<o){ rA[tid]+=rA[tid+o]; rB[tid]+=rB[tid+o]; rC[tid]=fmaxf(rC[tid],rC[tid+o]); }
        __syncthreads();
    }
    if (tid==0){ sS1 = rA[0]; sS2 = rB[0]; }
    float Mv = rC[0];
    __syncthreads();

    float Se = 0.f;
    for (int d = tid; d < 1024; d += 256) Se += expf(su[d] - Mv);
    rA[tid] = Se;
    __syncthreads();
    for (int o=128;o>0;o>>=1){ if (tid<o) rA[tid]+=rA[tid+o]; __syncthreads(); }
    if (tid==0)
        bmat[q*NSUP + s] = sS1 + sS2 - 1024.f*(Mv + logf(rA[0]));
}

__global__ void dis_kernel(const float* __restrict__ bmat,
                           const int* __restrict__ sy,
                           float* __restrict__ dis)
{
    int q = blockIdx.x;
    __shared__ float row[NSUP];
    __shared__ float red[128];
    int tid = threadIdx.x;
    float m = -1e30f;
    for (int s = tid; s < NSUP; s += 128){ row[s] = bmat[q*NSUP+s]; m = fmaxf(m, row[s]); }
    red[tid] = m; __syncthreads();
    for (int o=64;o>0;o>>=1){ if (tid<o) red[tid]=fmaxf(red[tid],red[tid+o]); __syncthreads(); }
    float mv = red[0]; __syncthreads();
    float se = 0.f;
    for (int s = tid; s < NSUP; s += 128) se += expf(row[s]-mv);
    red[tid] = se; __syncthreads();
    for (int o=64;o>0;o>>=1){ if (tid<o) red[tid]+=red[tid+o]; __syncthreads(); }
    float lse = mv + logf(red[0]);
    if (tid < NCLS){
        float sum = 0.f, cntc = 0.f;
        for (int s=0;s<NSUP;s++) if (sy[s]==tid){ sum += row[s]-lse; cntc += 1.f; }
        dis[q*NCLS+tid] = sum / fmaxf(cntc, 1.f);
    }
}

__global__ void center_kernel(const float* __restrict__ feat,
                              const int* __restrict__ sy,
                              const float* __restrict__ center,
                              float* __restrict__ outp)
{
    int c = blockIdx.x;
    int d = blockIdx.y*256 + threadIdx.x;
    __shared__ int ssy[NSUP];
    for (int s = threadIdx.x; s < NSUP; s += 256) ssy[s] = sy[s];
    __syncthreads();
    float sum = 0.f, cnt = 0.f;
    for (int s=0;s<NSUP;s++) if (ssy[s]==c){ sum += feat[(size_t)s*1024 + d]; cnt += 1.f; }
    outp[c*1024 + d] = (sum/fmaxf(cnt,1.f))*0.5f + 0.25f*center[c*1024 + d];
}

__global__ void loss_kernel(const float* __restrict__ dis,
                            const int* __restrict__ qy,
                            float* __restrict__ outp)
{
    __shared__ float sl[32], sa[32];
    int q = threadIdx.x;
    float l = 0.f, a = 0.f;
    if (q < NQRY){
        const float* r = dis + q*NCLS;
        float best = -1e30f; int arg = 0; float m = -1e30f;
        for (int j=0;j<NCLS;j++){
            float v = r[j];
            if (v > best){ best = v; arg = j; }
            m = fmaxf(m, v);
        }
        float se = 0.f;
        for (int j=0;j<NCLS;j++) se += expf(r[j]-m);
        float lse = m + logf(se);
        int y = qy[q];
        l = lse - r[y];
        a = (arg == y) ? 1.f : 0.f;
    }
    sl[threadIdx.x] = l; sa[threadIdx.x] = a;
    __syncthreads();
    if (threadIdx.x == 0){
        float L=0.f, A=0.f;
        for (int i=0;i<32;i++){ L += sl[i]; A += sa[i]; }
        outp[0] = L; outp[1] = A;
    }
}

// ---------------- host launcher ----------------
extern "C" void kernel_launch(void* const* d_in, const int* in_sizes, int n_in,
                              void* d_out, int out_size)
{
    const float* support_x = (const float*)d_in[0];
    const int*   sup_ei    = (const int*)  d_in[1];
    const int*   sup_y     = (const int*)  d_in[3];
    const float* query_x   = (const float*)d_in[4];
    const int*   qry_ei    = (const int*)  d_in[5];
    const int*   qry_y     = (const int*)  d_in[7];
    const float* center    = (const float*)d_in[8];
    const float* cw1       = (const float*)d_in[9];
    const float* cb1       = (const float*)d_in[10];
    const float* cw_rest   = (const float*)d_in[11];
    const float* cb_rest   = (const float*)d_in[12];
    const float* lin2_w    = (const float*)d_in[13];
    const float* lin2_b    = (const float*)d_in[14];
    const float* mlp_w     = (const float*)d_in[15];
    const float* mlp_b     = (const float*)d_in[16];
    float* out = (float*)d_out;

    int Es = in_sizes[1] / 2;
    int Eq = in_sizes[5] / 2;

    float *buf0, *buf1, *cat, *tmp, *h2, *feat, *agg, *cnt, *bmat, *dis;
    __nv_bfloat16 *ahi, *alo, *ahi2, *alo2, *wbp;
    cudaGetSymbolAddress((void**)&buf0, g_buf0);
    cudaGetSymbolAddress((void**)&buf1, g_buf1);
    cudaGetSymbolAddress((void**)&ahi,  g_ahi);
    cudaGetSymbolAddress((void**)&alo,  g_alo);
    cudaGetSymbolAddress((void**)&ahi2, g_ahi2);
    cudaGetSymbolAddress((void**)&alo2, g_alo2);
    cudaGetSymbolAddress((void**)&wbp,  g_wb);
    cudaGetSymbolAddress((void**)&cat,  g_cat);
    cudaGetSymbolAddress((void**)&tmp,  g_tmp);
    cudaGetSymbolAddress((void**)&h2,   g_h2);
    cudaGetSymbolAddress((void**)&feat, g_feat);
    cudaGetSymbolAddress((void**)&agg,  g_agg);
    cudaGetSymbolAddress((void**)&cnt,  g_cnt);
    cudaGetSymbolAddress((void**)&bmat, g_b);
    cudaGetSymbolAddress((void**)&dis,  g_dis);

    const size_t SMEMB  = 3*4608*8 + 3*2448*8;            // conv64e: 169344
    const size_t SMEMT2 = 92160 + 2*3*(size_t)130*144 + 128;  // tconv<128>: 204608
    const size_t SMEMT3 = 92160 + 2*3*(size_t)66*144  + 128;  // tconv<64>:  149312
    static int attr_done = 0;
    if (!attr_done){
        cudaFuncSetAttribute((const void*)tconv_kernel<128,true>, cudaFuncAttributeMaxDynamicSharedMemorySize, (int)SMEMT2);
        cudaFuncSetAttribute((const void*)tconv_kernel<64,false>, cudaFuncAttributeMaxDynamicSharedMemorySize, (int)SMEMT3);
        cudaFuncSetAttribute(conv64e_kernel<32>, cudaFuncAttributeMaxDynamicSharedMemorySize, (int)SMEMB);
        cudaFuncSetAttribute(conv64e_kernel<16>, cudaFuncAttributeMaxDynamicSharedMemorySize, (int)SMEMB);
        attr_done = 1;
    }

    const int NG = (NTOT*1024 + 255)/256;
    const int WSTR = 64*64*9;

    // capture slot = launch #4 -> tconv<128>
    wb2_kernel<<<(2*73728 + 255)/256, 256>>>(cw_rest, wbp);                         // #1
    conv1n_kernel<<<dim3(512, NTOT), 512>>>(support_x, query_x, cw1, cb1, buf0);    // #2
    tr_kernel<<<dim3(128, NTOT), 256>>>(buf0, ahi, alo);                            // #3
    tconv_kernel<128,true><<<dim3(2, NTOT), 256, SMEMT2>>>(ahi, alo, wbp, cb_rest,
                                                           nullptr, ahi2, alo2);    // #4 captured
    tconv_kernel<64,false><<<dim3(2, NTOT), 128, SMEMT3>>>(ahi2, alo2, wbp + 73728,
                                                           cb_rest + 64, buf0, nullptr, nullptr);
    conv64e_kernel<32><<<dim3( 4, NTOT), 512, SMEMB>>>(buf0, cw_rest+2*WSTR, cb_rest+128, buf1, 64*16*16);
    conv64e_kernel<16><<<dim3( 1, NTOT), 512, SMEMB>>>(buf1, cw_rest+3*WSTR, cb_rest+192, buf0, 64*8*8);
    conv64_kernel<8,4><<<dim3( 1, NTOT), 128>>>(buf0, cw_rest+4*WSTR, cb_rest+256, cat, 2048);

    zero_kernel<<<NG,256>>>(agg, NTOT*1024);
    zero_kernel<<<1,256>>>(cnt, NTOT);

    // ---- graph conv 1 ----
    scatter_kernel<<<Es,256>>>(cat, 2048, 0, sup_ei, Es, 0,    agg, cnt);
    scatter_kernel<<<Eq,256>>>(cat, 2048, 0, qry_ei, Eq, NSUP, agg, cnt);
    combine_kernel<<<NG,256>>>(cat, 2048, 0, agg, cnt, tmp, 1024, 0);

    gemm_bias_kernel<<<dim3(16,(NTOT+15)/16),256>>>(tmp, 1024, lin2_w, lin2_b, h2, NTOT, 1024);

    // ---- graph conv 2 ----
    zero_kernel<<<NG,256>>>(agg, NTOT*1024);
    zero_kernel<<<1,256>>>(cnt, NTOT);
    scatter_kernel<<<Es,256>>>(h2, 1024, 0, sup_ei, Es, 0,    agg, cnt);
    scatter_kernel<<<Eq,256>>>(h2, 1024, 0, qry_ei, Eq, NSUP, agg, cnt);
    combine_kernel<<<NG,256>>>(h2, 1024, 0, agg, cnt, cat, 2048, 1024);

    gemm_bias_kernel<<<dim3(16,(NTOT+15)/16),256>>>(cat, 2048, mlp_w, mlp_b, feat, NTOT, 2048);

    pair_kernel<<<dim3(NSUP, NQRY), 256>>>(feat, center, bmat);
    dis_kernel<<<NQRY,128>>>(bmat, sup_y, dis);

    center_kernel<<<dim3(NCLS,4),256>>>(feat, sup_y, center, out + 2);
    loss_kernel<<<1,32>>>(dis, qry_y, out);
}